// round 14
// baseline (speedup 1.0000x reference)
#include <cuda_runtime.h>
#include <cuda_bf16.h>
#include <cstdint>

// ---------------------------------------------------------------------------
// Problem constants
// ---------------------------------------------------------------------------
#define HH 38
#define WW 63
#define NP (HH*WW)          // 2394 pixels
#define CIN 512
#define AA 9
#define NANCH (NP*AA)       // 21546
#define SORTN 32768
#define PRE_NMS 6000
#define POST_NMS 300
#define K_CONV (CIN*9)      // 4608
#define K_FC6 (512*49)      // 25088
#define NCLS 32
#define NWRD 94             // ceil(6000/64)
#define NW32 188            // ceil(6000/32)

// ---------------------------------------------------------------------------
// Static device scratch (no allocation allowed)
// ---------------------------------------------------------------------------
__device__ float g_col[NP * K_CONV];          // im2col  (~44MB)
__device__ float g_rpn[NP * CIN];             // rpn conv out, HWC
__device__ float g_featT[NP * CIN];           // transposed features (HWC)
__device__ float g_sb[NP * 54];               // merged score(18)+bbox(36) out
__device__ float g_sbw[54 * 512];             // merged conv weights
__device__ float g_sbb[54];
__device__ float g_hw[160 * 4096];            // merged head weights
__device__ float g_hb[160];
__device__ float g_hd[POST_NMS * 160];        // merged head out
__device__ float g_part[8 * 300 * 4096];      // split-K partials (max: fc6)
__device__ float g_part2[4 * NP * 512];       // split-K partials (NP-row gemms)
__device__ float g_props[NANCH * 4];
__device__ float g_psc[NANCH];
__device__ unsigned long long g_keys[SORTN];
__device__ float g_pb[PRE_NMS * 4];
__device__ float g_ps[PRE_NMS];
__device__ unsigned long long g_mask[(size_t)PRE_NMS * NWRD];  // 4.5MB
__device__ float g_rois[POST_NMS * 4];
__device__ float g_pooled[POST_NMS * K_FC6];  // (~30MB)
__device__ float g_x6[POST_NMS * 4096];
__device__ float g_x7[POST_NMS * 4096];

// 9 anchors (precomputed to match _generate_anchors incl. numpy banker's rounding)
__constant__ float c_anch[9][4] = {
    {-84.f,  -40.f,  99.f,  55.f},
    {-176.f, -88.f,  191.f, 103.f},
    {-360.f, -184.f, 375.f, 199.f},
    {-56.f,  -56.f,  71.f,  71.f},
    {-120.f, -120.f, 135.f, 135.f},
    {-248.f, -248.f, 263.f, 263.f},
    {-36.f,  -80.f,  51.f,  95.f},
    {-80.f,  -168.f, 95.f,  183.f},
    {-168.f, -344.f, 183.f, 359.f}};

__device__ __forceinline__ unsigned fkey_asc(float f) {
    unsigned u = __float_as_uint(f);
    return (u & 0x80000000u) ? ~u : (u | 0x80000000u);
}
__device__ __forceinline__ float neg_inf_f() { return __int_as_float(0xff800000); }

// ---------------------------------------------------------------------------
// Warp-MMA GEMM (bf16-split, fp32 accum): C[M,N] = A[M,K]*B[N,K]^T.
// CTA tile 64(M) x 128(N), BK=32, 8 warps of 32x32 (wm:2 x wn:4).
// ldmatrix fragment loads. A*B ~= Ahi*Bhi + Ahi*Blo + Alo*Bhi.
// (Exact R11 configuration - measured 1806us.)
// Requires: N % 128 == 0, (K/gridDim.z) % 32 == 0. Grid (mT, nT, S).
// ---------------------------------------------------------------------------
#define MPAD 40                      // bf16 elems per smem row (32 + 8 pad)
#define A_TILE (64 * MPAD * 2)       // 5120 B per A buffer (hi or lo)
#define B_TILE (128 * MPAD * 2)      // 10240 B per B buffer
#define MBUF (2 * A_TILE + 2 * B_TILE)   // 30720 B
#define MM2_SMEM (2 * MBUF)              // 61440 B

__device__ __forceinline__ void mma16816(float* c, const uint32_t* a, const uint32_t* b) {
    asm volatile(
        "mma.sync.aligned.m16n8k16.row.col.f32.bf16.bf16.f32 "
        "{%0,%1,%2,%3}, {%4,%5,%6,%7}, {%8,%9}, {%0,%1,%2,%3};"
        : "+f"(c[0]), "+f"(c[1]), "+f"(c[2]), "+f"(c[3])
        : "r"(a[0]), "r"(a[1]), "r"(a[2]), "r"(a[3]), "r"(b[0]), "r"(b[1]));
}

__device__ __forceinline__ void ldsm4(uint32_t* r, uint32_t addr) {
    asm volatile(
        "ldmatrix.sync.aligned.m8n8.x4.shared.b16 {%0,%1,%2,%3}, [%4];"
        : "=r"(r[0]), "=r"(r[1]), "=r"(r[2]), "=r"(r[3]) : "r"(addr));
}

__device__ __forceinline__ void f4_to_bf(const float4& v, uint32_t& hi0, uint32_t& hi1,
                                         uint32_t& lo0, uint32_t& lo1) {
    __nv_bfloat162 h0, h1, l0, l1;
    h0.x = __float2bfloat16(v.x); h0.y = __float2bfloat16(v.y);
    h1.x = __float2bfloat16(v.z); h1.y = __float2bfloat16(v.w);
    l0.x = __float2bfloat16(v.x - __bfloat162float(h0.x));
    l0.y = __float2bfloat16(v.y - __bfloat162float(h0.y));
    l1.x = __float2bfloat16(v.z - __bfloat162float(h1.x));
    l1.y = __float2bfloat16(v.w - __bfloat162float(h1.y));
    hi0 = *(uint32_t*)&h0; hi1 = *(uint32_t*)&h1;
    lo0 = *(uint32_t*)&l0; lo1 = *(uint32_t*)&l1;
}

__global__ void __launch_bounds__(256)
mma_gemm(const float* __restrict__ A, const float* __restrict__ B,
         const float* __restrict__ bias, float* __restrict__ C,
         float* __restrict__ part, int M, int N, int K, int relu) {
    extern __shared__ char smem[];
    const int tid = threadIdx.x;
    const int wid = tid >> 5;
    const int lane = tid & 31;

    const int S = gridDim.z;
    const int Kc = K / S;
    const int k0 = blockIdx.z * Kc;
    const int m0 = blockIdx.x * 64;
    const int n0 = blockIdx.y * 128;
    const int nChunks = Kc >> 5;

    const int wm = wid & 1;          // rows 32*wm  (0..1)
    const int wn = wid >> 1;         // cols 32*wn  (0..3)

    float acc[2][4][4];
#pragma unroll
    for (int i = 0; i < 2; i++)
#pragma unroll
        for (int j = 0; j < 4; j++)
#pragma unroll
            for (int q = 0; q < 4; q++) acc[i][j][q] = 0.f;

    // ldmatrix per-lane byte offsets within tiles
    const uint32_t smem_u = (uint32_t)__cvta_generic_to_shared(smem);
    const int r8 = lane & 7;
    const int amr = ((lane >> 3) & 1) << 3;   // A: +0/+8 rows (matrix 1,3)
    const int amc = ((lane >> 4) & 1) << 3;   // A: +0/+8 k    (matrix 2,3)
    const int bnr = ((lane >> 4) & 1) << 3;   // B: +0/+8 n within pair
    const int bkc = ((lane >> 3) & 1) << 3;   // B: +0/+8 k
    const uint32_t aLane = (uint32_t)((wm * 32 + amr + r8) * (MPAD * 2) + amc * 2);
    const uint32_t bLane = (uint32_t)((wn * 32 + bnr + r8) * (MPAD * 2) + bkc * 2);

    // loader coords
    int aRow[2], aC4[2], bRow[4], bC4[4];
#pragma unroll
    for (int q = 0; q < 2; q++) {
        int e = q * 256 + tid;
        aRow[q] = e >> 3;
        aC4[q] = (e & 7) << 2;
    }
#pragma unroll
    for (int q = 0; q < 4; q++) {
        int e = q * 256 + tid;
        bRow[q] = e >> 3;
        bC4[q] = (e & 7) << 2;
    }
    int aRowG[2];
#pragma unroll
    for (int q = 0; q < 2; q++) {
        int r = m0 + aRow[q];
        aRowG[q] = (r < M) ? r : (M - 1);
    }

    float4 ra[2], rb[4];
    auto issue_loads = [&](int it) {
        int gk = k0 + it * 32;
#pragma unroll
        for (int q = 0; q < 2; q++)
            ra[q] = *(const float4*)(A + (size_t)aRowG[q] * K + gk + aC4[q]);
#pragma unroll
        for (int q = 0; q < 4; q++)
            rb[q] = *(const float4*)(B + (size_t)(n0 + bRow[q]) * K + gk + bC4[q]);
    };
    auto cvt_store = [&](int b) {
        char* buf = smem + b * MBUF;
        char* bAhi = buf;
        char* bAlo = buf + A_TILE;
        char* bBhi = buf + 2 * A_TILE;
        char* bBlo = bBhi + B_TILE;
#pragma unroll
        for (int q = 0; q < 2; q++) {
            uint32_t h0, h1, l0, l1;
            f4_to_bf(ra[q], h0, h1, l0, l1);
            size_t off = (size_t)aRow[q] * (MPAD * 2) + aC4[q] * 2;
            *(uint2*)(bAhi + off) = make_uint2(h0, h1);
            *(uint2*)(bAlo + off) = make_uint2(l0, l1);
        }
#pragma unroll
        for (int q = 0; q < 4; q++) {
            uint32_t h0, h1, l0, l1;
            f4_to_bf(rb[q], h0, h1, l0, l1);
            size_t off = (size_t)bRow[q] * (MPAD * 2) + bC4[q] * 2;
            *(uint2*)(bBhi + off) = make_uint2(h0, h1);
            *(uint2*)(bBlo + off) = make_uint2(l0, l1);
        }
    };

    issue_loads(0);
    cvt_store(0);
    __syncthreads();

    for (int it = 0; it < nChunks; ++it) {
        const bool more = (it + 1 < nChunks);
        if (more) issue_loads(it + 1);     // LDGs in flight during MMA section

        const uint32_t base = smem_u + (it & 1) * MBUF;
        const uint32_t aHiB = base + aLane;
        const uint32_t aLoB = base + A_TILE + aLane;
        const uint32_t bHiB = base + 2 * A_TILE + bLane;
        const uint32_t bLoB = base + 2 * A_TILE + B_TILE + bLane;
#pragma unroll
        for (int ks = 0; ks < 2; ks++) {
            const uint32_t kb = (uint32_t)(ks * 16 * 2);   // byte offset of k-step
            uint32_t ah[2][4], al[2][4];
#pragma unroll
            for (int mf = 0; mf < 2; mf++) {
                uint32_t moff = (uint32_t)(mf * 16 * (MPAD * 2)) + kb;
                ldsm4(ah[mf], aHiB + moff);
                ldsm4(al[mf], aLoB + moff);
            }
            uint32_t bh[4][2], bl[4][2];
#pragma unroll
            for (int p = 0; p < 2; p++) {
                uint32_t poff = (uint32_t)(p * 16 * (MPAD * 2)) + kb;
                uint32_t t4[4];
                ldsm4(t4, bHiB + poff);
                bh[2 * p][0] = t4[0]; bh[2 * p][1] = t4[1];
                bh[2 * p + 1][0] = t4[2]; bh[2 * p + 1][1] = t4[3];
                ldsm4(t4, bLoB + poff);
                bl[2 * p][0] = t4[0]; bl[2 * p][1] = t4[1];
                bl[2 * p + 1][0] = t4[2]; bl[2 * p + 1][1] = t4[3];
            }
#pragma unroll
            for (int nf = 0; nf < 4; nf++) {
#pragma unroll
                for (int mf = 0; mf < 2; mf++) {
                    mma16816(acc[mf][nf], ah[mf], bh[nf]);
                    mma16816(acc[mf][nf], ah[mf], bl[nf]);
                    mma16816(acc[mf][nf], al[mf], bh[nf]);
                }
            }
        }
        if (more) cvt_store((it + 1) & 1); // consume LDG results after MMA cover
        __syncthreads();
    }

    // epilogue
    const int g = lane >> 2;
    const int tg = lane & 3;
#pragma unroll
    for (int mf = 0; mf < 2; mf++) {
        int row0 = m0 + wm * 32 + mf * 16 + g;
        int row1 = row0 + 8;
#pragma unroll
        for (int nf = 0; nf < 4; nf++) {
            int col = n0 + wn * 32 + nf * 8 + 2 * tg;
            if (S == 1) {
                if (row0 < M) {
                    float v0 = acc[mf][nf][0] + bias[col];
                    float v1 = acc[mf][nf][1] + bias[col + 1];
                    if (relu) { v0 = fmaxf(v0, 0.f); v1 = fmaxf(v1, 0.f); }
                    C[(size_t)row0 * N + col] = v0;
                    C[(size_t)row0 * N + col + 1] = v1;
                }
                if (row1 < M) {
                    float v2 = acc[mf][nf][2] + bias[col];
                    float v3 = acc[mf][nf][3] + bias[col + 1];
                    if (relu) { v2 = fmaxf(v2, 0.f); v3 = fmaxf(v3, 0.f); }
                    C[(size_t)row1 * N + col] = v2;
                    C[(size_t)row1 * N + col + 1] = v3;
                }
            } else {
                float* P = part + (size_t)blockIdx.z * M * N;
                if (row0 < M) {
                    P[(size_t)row0 * N + col] = acc[mf][nf][0];
                    P[(size_t)row0 * N + col + 1] = acc[mf][nf][1];
                }
                if (row1 < M) {
                    P[(size_t)row1 * N + col] = acc[mf][nf][2];
                    P[(size_t)row1 * N + col + 1] = acc[mf][nf][3];
                }
            }
        }
    }
}

// ---------------------------------------------------------------------------
// im2col for 3x3 pad 1 conv on [512,38,63]
// ---------------------------------------------------------------------------
__global__ void im2col_kernel(const float* __restrict__ feat, float* __restrict__ col) {
    int idx = blockIdx.x * blockDim.x + threadIdx.x;
    if (idx >= NP * K_CONV) return;
    int p = idx / K_CONV;
    int k = idx - p * K_CONV;
    int ic = k / 9;
    int r = k - ic * 9;
    int ky = r / 3, kx = r - ky * 3;
    int y0 = p / WW, x0 = p - y0 * WW;
    int y = y0 + ky - 1, x = x0 + kx - 1;
    float v = 0.f;
    if (y >= 0 && y < HH && x >= 0 && x < WW)
        v = feat[ic * NP + y * WW + x];
    col[idx] = v;
}

// CHW -> HWC transpose of the input features (32x32 smem tiles)
__global__ void transpose_feat(const float* __restrict__ feat, float* __restrict__ featT) {
    __shared__ float tile[32][33];
    int p0 = blockIdx.x * 32, c0 = blockIdx.y * 32;
    int p = p0 + threadIdx.x;
    int c = c0 + threadIdx.y;
    if (p < NP) tile[threadIdx.y][threadIdx.x] = feat[(size_t)c * NP + p];
    __syncthreads();
    int pw = p0 + threadIdx.y, cw = c0 + threadIdx.x;
    if (pw < NP) featT[(size_t)pw * CIN + cw] = tile[threadIdx.x][threadIdx.y];
}

// Weight concat kernels (merge small GEMMs)
__global__ void concat_sb(const float* __restrict__ sw, const float* __restrict__ sb,
                          const float* __restrict__ bw, const float* __restrict__ bb,
                          float* __restrict__ w, float* __restrict__ b) {
    int idx = blockIdx.x * blockDim.x + threadIdx.x;
    if (idx < 54 * 512) {
        int row = idx / 512, col = idx - row * 512;
        w[idx] = (row < 18) ? sw[row * 512 + col] : bw[(row - 18) * 512 + col];
    }
    if (idx < 54) b[idx] = (idx < 18) ? sb[idx] : bb[idx - 18];
}

__global__ void concat_hd(const float* __restrict__ sfw, const float* __restrict__ sfb,
                          const float* __restrict__ bfw, const float* __restrict__ bfb,
                          float* __restrict__ w, float* __restrict__ b) {
    int idx = blockIdx.x * blockDim.x + threadIdx.x;
    if (idx < 160 * 4096) {
        int row = idx / 4096, col = idx - row * 4096;
        w[idx] = (row < 32) ? sfw[row * 4096 + col] : bfw[(row - 32) * 4096 + col];
    }
    if (idx < 160) b[idx] = (idx < 32) ? sfb[idx] : bfb[idx - 32];
}

// ---------------------------------------------------------------------------
// Scalar SGEMM (conv1, merged 1x1 conv, merged heads)
// ---------------------------------------------------------------------------
__global__ void __launch_bounds__(256, 2)
sgemm_tn(const float* __restrict__ A, const float* __restrict__ B,
         const float* __restrict__ bias, float* __restrict__ C,
         float* __restrict__ part, int M, int N, int K, int relu) {
    const int S = gridDim.z;
    const int Kc = K / S;
    const int k0 = blockIdx.z * Kc;
    const int m0 = blockIdx.x * 128;
    const int n0 = blockIdx.y * 128;

    __shared__ float As[2][8][132];
    __shared__ float Bs[2][8][132];

    const int tid = threadIdx.x;
    const int lr = tid >> 1;
    const int lc = (tid & 1) << 2;

    int arow = m0 + lr; if (arow >= M) arow = M - 1;
    int brow = n0 + lr; if (brow >= N) brow = N - 1;
    const float* Ap = A + (size_t)arow * K + k0 + lc;
    const float* Bp = B + (size_t)brow * K + k0 + lc;

    const int tx = tid & 15, ty = tid >> 4;
    const int mm = ty << 3, nn = tx << 3;

    float acc[8][8];
#pragma unroll
    for (int i = 0; i < 8; i++)
#pragma unroll
        for (int j = 0; j < 8; j++) acc[i][j] = 0.f;

    const int nIter = Kc >> 3;
    float4 a4 = *(const float4*)Ap;
    float4 b4 = *(const float4*)Bp;
    As[0][lc + 0][lr] = a4.x; As[0][lc + 1][lr] = a4.y;
    As[0][lc + 2][lr] = a4.z; As[0][lc + 3][lr] = a4.w;
    Bs[0][lc + 0][lr] = b4.x; Bs[0][lc + 1][lr] = b4.y;
    Bs[0][lc + 2][lr] = b4.z; Bs[0][lc + 3][lr] = b4.w;
    __syncthreads();

    int buf = 0;
    for (int it = 0; it < nIter; ++it) {
        float4 a4n, b4n;
        const bool more = (it + 1 < nIter);
        if (more) {
            a4n = *(const float4*)(Ap + (size_t)(it + 1) * 8);
            b4n = *(const float4*)(Bp + (size_t)(it + 1) * 8);
        }
#pragma unroll
        for (int kk = 0; kk < 8; ++kk) {
            float4 a0 = *(const float4*)&As[buf][kk][mm];
            float4 a1 = *(const float4*)&As[buf][kk][mm + 4];
            float4 b0 = *(const float4*)&Bs[buf][kk][nn];
            float4 b1 = *(const float4*)&Bs[buf][kk][nn + 4];
            float ar[8] = {a0.x, a0.y, a0.z, a0.w, a1.x, a1.y, a1.z, a1.w};
            float br[8] = {b0.x, b0.y, b0.z, b0.w, b1.x, b1.y, b1.z, b1.w};
#pragma unroll
            for (int i = 0; i < 8; i++)
#pragma unroll
                for (int j = 0; j < 8; j++) acc[i][j] += ar[i] * br[j];
        }
        if (more) {
            int nb = buf ^ 1;
            As[nb][lc + 0][lr] = a4n.x; As[nb][lc + 1][lr] = a4n.y;
            As[nb][lc + 2][lr] = a4n.z; As[nb][lc + 3][lr] = a4n.w;
            Bs[nb][lc + 0][lr] = b4n.x; Bs[nb][lc + 1][lr] = b4n.y;
            Bs[nb][lc + 2][lr] = b4n.z; Bs[nb][lc + 3][lr] = b4n.w;
            __syncthreads();
            buf = nb;
        }
    }

    if (S == 1) {
#pragma unroll
        for (int i = 0; i < 8; i++) {
            int gm = m0 + mm + i;
            if (gm >= M) continue;
#pragma unroll
            for (int j = 0; j < 8; j++) {
                int gn = n0 + nn + j;
                if (gn >= N) continue;
                float v = acc[i][j] + bias[gn];
                if (relu) v = fmaxf(v, 0.f);
                C[(size_t)gm * N + gn] = v;
            }
        }
    } else {
        float* P = part + (size_t)blockIdx.z * M * N;
#pragma unroll
        for (int i = 0; i < 8; i++) {
            int gm = m0 + mm + i;
            if (gm >= M) continue;
#pragma unroll
            for (int j = 0; j < 8; j++) {
                int gn = n0 + nn + j;
                if (gn >= N) continue;
                P[(size_t)gm * N + gn] = acc[i][j];
            }
        }
    }
}

// Deterministic split-K reduction: C = sum_z part[z] + bias (+relu)
__global__ void reduce_splits(const float* __restrict__ part, const float* __restrict__ bias,
                              float* __restrict__ C, int M, int N, int S, int relu) {
    int idx = blockIdx.x * blockDim.x + threadIdx.x;
    int total = M * N;
    if (idx >= total) return;
    float s = 0.f;
    for (int z = 0; z < S; z++) s += part[(size_t)z * total + idx];
    s += bias[idx % N];
    if (relu) s = fmaxf(s, 0.f);
    C[idx] = s;
}

// ---------------------------------------------------------------------------
// Proposal prep: reads merged sb [NP][54] (cols 0..17 score, 18..53 deltas)
// ---------------------------------------------------------------------------
__global__ void proposal_prep(const float* __restrict__ sbuf,
                              const float* __restrict__ info,
                              float* __restrict__ props, float* __restrict__ psc,
                              unsigned long long* __restrict__ keys) {
    int i = blockIdx.x * blockDim.x + threadIdx.x;
    if (i >= SORTN) return;
    if (i >= NANCH) { keys[i] = ~0ull; return; }
    int p = i / AA, a = i - p * AA;
    int hy = p / WW, wx = p - hy * WW;
    float shx = wx * 16.f, shy = hy * 16.f;
    float ax1 = c_anch[a][0] + shx, ay1 = c_anch[a][1] + shy;
    float ax2 = c_anch[a][2] + shx, ay2 = c_anch[a][3] + shy;
    float aw = ax2 - ax1 + 1.f, ah = ay2 - ay1 + 1.f;
    float cx = ax1 + 0.5f * aw, cy = ay1 + 0.5f * ah;
    const float* row = sbuf + (size_t)p * 54;
    const float* d = row + 18 + a * 4;
    float pcx = d[0] * aw + cx;
    float pcy = d[1] * ah + cy;
    float pw_ = expf(d[2]) * aw;
    float ph_ = expf(d[3]) * ah;
    float imh = info[0], imw = info[1], sc = info[2];
    float x1 = fminf(fmaxf(pcx - 0.5f * pw_, 0.f), imw - 1.f);
    float y1 = fminf(fmaxf(pcy - 0.5f * ph_, 0.f), imh - 1.f);
    float x2 = fminf(fmaxf(pcx + 0.5f * pw_, 0.f), imw - 1.f);
    float y2 = fminf(fmaxf(pcy + 0.5f * ph_, 0.f), imh - 1.f);
    bool ok = ((x2 - x1 + 1.f) >= 16.f * sc) && ((y2 - y1 + 1.f) >= 16.f * sc);
    float s0 = row[a];
    float s1 = row[a + 9];
    float m = fmaxf(s0, s1);
    float e0 = expf(s0 - m), e1 = expf(s1 - m);
    float prob = e1 / (e0 + e1);
    float score = ok ? prob : neg_inf_f();
    props[i * 4 + 0] = x1; props[i * 4 + 1] = y1;
    props[i * 4 + 2] = x2; props[i * 4 + 3] = y2;
    psc[i] = score;
    unsigned fk = fkey_asc(score);
    keys[i] = ((unsigned long long)(~fk) << 32) | (unsigned)i;
}

// ---------------------------------------------------------------------------
// Bitonic sort on 32768 u64 keys: 8192-wide local blocks + global passes.
// ---------------------------------------------------------------------------
__global__ void bitonic_local8k(unsigned long long* keys) {
    extern __shared__ unsigned long long s8[];
    int base = blockIdx.x * 8192, t = threadIdx.x;
#pragma unroll
    for (int q = 0; q < 8; q++) s8[t + q * 1024] = keys[base + t + q * 1024];
    __syncthreads();
    for (int k = 2; k <= 8192; k <<= 1) {
        for (int j = k >> 1; j > 0; j >>= 1) {
#pragma unroll
            for (int q = 0; q < 4; q++) {
                int p = t + q * 1024;
                int i = ((p & ~(j - 1)) << 1) | (p & (j - 1));
                int l = i + j;
                bool up = (((base + i) & k) == 0);
                unsigned long long a = s8[i], b = s8[l];
                if (up ? (a > b) : (a < b)) { s8[i] = b; s8[l] = a; }
            }
            __syncthreads();
        }
    }
#pragma unroll
    for (int q = 0; q < 8; q++) keys[base + t + q * 1024] = s8[t + q * 1024];
}

__global__ void bitonic_global_pass(unsigned long long* keys, int k, int j) {
    int p = blockIdx.x * blockDim.x + threadIdx.x;
    int i = ((p & ~(j - 1)) << 1) | (p & (j - 1));
    int l = i + j;
    bool up = ((i & k) == 0);
    unsigned long long a = keys[i], b = keys[l];
    if (up ? (a > b) : (a < b)) { keys[i] = b; keys[l] = a; }
}

__global__ void bitonic_tail8k(unsigned long long* keys, int k) {
    extern __shared__ unsigned long long s8[];
    int base = blockIdx.x * 8192, t = threadIdx.x;
#pragma unroll
    for (int q = 0; q < 8; q++) s8[t + q * 1024] = keys[base + t + q * 1024];
    __syncthreads();
    for (int j = 4096; j > 0; j >>= 1) {
#pragma unroll
        for (int q = 0; q < 4; q++) {
            int p = t + q * 1024;
            int i = ((p & ~(j - 1)) << 1) | (p & (j - 1));
            int l = i + j;
            bool up = (((base + i) & k) == 0);
            unsigned long long a = s8[i], b = s8[l];
            if (up ? (a > b) : (a < b)) { s8[i] = b; s8[l] = a; }
        }
        __syncthreads();
    }
#pragma unroll
    for (int q = 0; q < 8; q++) keys[base + t + q * 1024] = s8[t + q * 1024];
}

__global__ void gather_pre(const unsigned long long* __restrict__ keys,
                           const float* __restrict__ props, const float* __restrict__ psc,
                           float* __restrict__ pb, float* __restrict__ ps) {
    int i = blockIdx.x * blockDim.x + threadIdx.x;
    if (i >= PRE_NMS) return;
    unsigned idx = (unsigned)(keys[i] & 0xFFFFFFFFull);
    pb[i * 4 + 0] = props[idx * 4 + 0];
    pb[i * 4 + 1] = props[idx * 4 + 1];
    pb[i * 4 + 2] = props[idx * 4 + 2];
    pb[i * 4 + 3] = props[idx * 4 + 3];
    ps[i] = psc[idx];
}

// ---------------------------------------------------------------------------
// NMS stage 1: pairwise suppression bitmask (upper triangle: i suppresses j>i).
// Lower-triangle blocks skipped: those words are never non-zero and g_mask is
// zero-initialized (condition is data-independent), so reads stay correct.
// ---------------------------------------------------------------------------
__global__ void nms_mask_kernel(const float* __restrict__ pb,
                                unsigned long long* __restrict__ mask) {
    int jb = blockIdx.x;
    int ib = blockIdx.y;
    if (jb * 64 + 63 <= ib * 64) return;   // whole block lower-triangle
    int t = threadIdx.x;
    __shared__ float cb[64][5];
    int j0 = jb * 64;
    if (j0 + t < PRE_NMS) {
        float x1 = pb[(j0 + t) * 4 + 0];
        float y1 = pb[(j0 + t) * 4 + 1];
        float x2 = pb[(j0 + t) * 4 + 2];
        float y2 = pb[(j0 + t) * 4 + 3];
        cb[t][0] = x1; cb[t][1] = y1; cb[t][2] = x2; cb[t][3] = y2;
        cb[t][4] = (x2 - x1 + 1.f) * (y2 - y1 + 1.f);
    }
    __syncthreads();
    int i = ib * 64 + t;
    if (i >= PRE_NMS) return;
    unsigned long long w = 0ull;
    if (j0 + 63 > i) {
        float bx1 = pb[i * 4 + 0], by1 = pb[i * 4 + 1];
        float bx2 = pb[i * 4 + 2], by2 = pb[i * 4 + 3];
        float ba = (bx2 - bx1 + 1.f) * (by2 - by1 + 1.f);
        int cols = min(64, PRE_NMS - j0);
        for (int tt = 0; tt < cols; tt++) {
            int j = j0 + tt;
            if (j <= i) continue;
            float xx1 = fmaxf(bx1, cb[tt][0]);
            float yy1 = fmaxf(by1, cb[tt][1]);
            float xx2 = fminf(bx2, cb[tt][2]);
            float yy2 = fminf(by2, cb[tt][3]);
            float inter = fmaxf(xx2 - xx1 + 1.f, 0.f) * fmaxf(yy2 - yy1 + 1.f, 0.f);
            float iou = inter / (ba + cb[tt][4] - inter);
            if (iou > 0.7f) w |= (1ull << tt);
        }
    }
    mask[(size_t)i * NWRD + jb] = w;
}

// ---------------------------------------------------------------------------
// NMS stage 2: block-parallel greedy scan over an alive bitmap.
// ---------------------------------------------------------------------------
__global__ void nms_scan2(const unsigned long long* __restrict__ mask,
                          const float* __restrict__ pb,
                          const float* __restrict__ ps,
                          float* __restrict__ rois, float* __restrict__ out_rois) {
    __shared__ unsigned alive[NW32];
    __shared__ int wmin[8];
    __shared__ int s_best, s_kept;
    int t = threadIdx.x;
    int lane = t & 31, wid = t >> 5;

    for (int w = wid; w < NW32; w += 8) {
        int c = w * 32 + lane;
        bool fin = (c < PRE_NMS) && (ps[c] > -3.0e38f);
        unsigned m = __ballot_sync(0xFFFFFFFFu, fin);
        if (lane == 0) alive[w] = m;
    }
    if (t == 0) s_kept = 0;
    __syncthreads();

    for (int r = 0; r < POST_NMS; r++) {
        int cand = 0x7FFFFFFF;
        if (t < NW32) {
            unsigned w = alive[t];
            if (w) cand = t * 32 + __ffs(w) - 1;
        }
#pragma unroll
        for (int o = 16; o; o >>= 1) cand = min(cand, __shfl_xor_sync(0xFFFFFFFFu, cand, o));
        if (lane == 0) wmin[wid] = cand;
        __syncthreads();
        if (t == 0) {
            int b = wmin[0];
#pragma unroll
            for (int q = 1; q < 8; q++) b = min(b, wmin[q]);
            s_best = b;
        }
        __syncthreads();
        int i = s_best;
        if (i == 0x7FFFFFFF) break;
        if (t == 0) {
            float x1 = pb[i * 4 + 0], y1 = pb[i * 4 + 1];
            float x2 = pb[i * 4 + 2], y2 = pb[i * 4 + 3];
            rois[r * 4 + 0] = x1; rois[r * 4 + 1] = y1;
            rois[r * 4 + 2] = x2; rois[r * 4 + 3] = y2;
            out_rois[r * 4 + 0] = x1; out_rois[r * 4 + 1] = y1;
            out_rois[r * 4 + 2] = x2; out_rois[r * 4 + 3] = y2;
            s_kept = r + 1;
        }
        if (t < NW32) {
            const unsigned* row = (const unsigned*)(mask + (size_t)i * NWRD);
            unsigned a = alive[t] & ~row[t];
            if (t == (i >> 5)) a &= ~(1u << (i & 31));
            alive[t] = a;
        }
        __syncthreads();
    }
    __syncthreads();
    if (t == 0) {
        int kept = s_kept;
        float x1 = pb[0], y1 = pb[1], x2 = pb[2], y2 = pb[3];
        for (int r = kept; r < POST_NMS; r++) {
            rois[r * 4 + 0] = x1; rois[r * 4 + 1] = y1;
            rois[r * 4 + 2] = x2; rois[r * 4 + 3] = y2;
            out_rois[r * 4 + 0] = x1; out_rois[r * 4 + 1] = y1;
            out_rois[r * 4 + 2] = x2; out_rois[r * 4 + 3] = y2;
        }
    }
}

// ---------------------------------------------------------------------------
// ROI max-pool 7x7, HWC layout: block per roi, 256 threads x 2 channels each
// (float2). Bin boundaries and per-channel max order identical to reference.
// ---------------------------------------------------------------------------
__global__ void __launch_bounds__(256)
roipool_hwc(const float* __restrict__ featT, const float* __restrict__ rois,
            float* __restrict__ pooled) {
    int r = blockIdx.x;
    int t = threadIdx.x;
    __shared__ int hs[7], he[7], ws_[7], we[7];
    if (t == 0) {
        float x1 = rois[r * 4], y1 = rois[r * 4 + 1], x2 = rois[r * 4 + 2], y2 = rois[r * 4 + 3];
        float rsw = rintf(x1 * 0.0625f), rsh = rintf(y1 * 0.0625f);
        float rew = rintf(x2 * 0.0625f), reh = rintf(y2 * 0.0625f);
        float bw = fmaxf(rew - rsw + 1.f, 1.f) * (1.f / 7.f);
        float bh = fmaxf(reh - rsh + 1.f, 1.f) * (1.f / 7.f);
        for (int p = 0; p < 7; p++) {
            float fp = (float)p;
            hs[p] = (int)fminf(fmaxf(floorf(fp * bh) + rsh, 0.f), (float)HH);
            he[p] = (int)fminf(fmaxf(ceilf((fp + 1.f) * bh) + rsh, 0.f), (float)HH);
            ws_[p] = (int)fminf(fmaxf(floorf(fp * bw) + rsw, 0.f), (float)WW);
            we[p] = (int)fminf(fmaxf(ceilf((fp + 1.f) * bw) + rsw, 0.f), (float)WW);
        }
    }
    __syncthreads();
    const float2* fT = (const float2*)featT;    // [pix][256] float2
    float* dst = pooled + (size_t)r * K_FC6;
    int c = 2 * t;
#pragma unroll 1
    for (int bin = 0; bin < 49; bin++) {
        int ph = bin / 7, pw = bin - ph * 7;
        float2 m = make_float2(-1e30f, -1e30f);
        for (int y = hs[ph]; y < he[ph]; y++) {
            const float2* rowp = fT + (size_t)(y * WW) * 256 + t;
            for (int x = ws_[pw]; x < we[pw]; x++) {
                float2 v = rowp[(size_t)x * 256];
                m.x = fmaxf(m.x, v.x);
                m.y = fmaxf(m.y, v.y);
            }
        }
        dst[(c + 0) * 49 + bin] = (m.x < -1e29f) ? 0.f : m.x;
        dst[(c + 1) * 49 + bin] = (m.y < -1e29f) ? 0.f : m.y;
    }
}

// ---------------------------------------------------------------------------
// Heads output: softmax over 32 classes (warp 0) + box copy (threads 32..159)
// ---------------------------------------------------------------------------
__global__ void heads_out(const float* __restrict__ hd, float* __restrict__ out) {
    int r = blockIdx.x;
    int t = threadIdx.x;
    if (t < 32) {
        float v = hd[r * 160 + t];
        float m = v;
#pragma unroll
        for (int o = 16; o; o >>= 1) m = fmaxf(m, __shfl_xor_sync(0xFFFFFFFFu, m, o));
        float e = expf(v - m);
        float s = e;
#pragma unroll
        for (int o = 16; o; o >>= 1) s += __shfl_xor_sync(0xFFFFFFFFu, s, o);
        out[r * NCLS + t] = e / s;
    } else {
        out[9600 + r * 128 + (t - 32)] = hd[r * 160 + t];
    }
}

// ---------------------------------------------------------------------------
// Launch
// ---------------------------------------------------------------------------
extern "C" void kernel_launch(void* const* d_in, const int* in_sizes, int n_in,
                              void* d_out, int out_size) {
    const float* feat  = (const float*)d_in[0];
    const float* info  = (const float*)d_in[1];
    const float* c1w   = (const float*)d_in[2];
    const float* c1b   = (const float*)d_in[3];
    const float* sw    = (const float*)d_in[4];
    const float* sb    = (const float*)d_in[5];
    const float* bw    = (const float*)d_in[6];
    const float* bb    = (const float*)d_in[7];
    const float* fc6w  = (const float*)d_in[8];
    const float* fc6b  = (const float*)d_in[9];
    const float* fc7w  = (const float*)d_in[10];
    const float* fc7b  = (const float*)d_in[11];
    const float* sfw   = (const float*)d_in[12];
    const float* sfb   = (const float*)d_in[13];
    const float* bfw   = (const float*)d_in[14];
    const float* bfb   = (const float*)d_in[15];
    float* out = (float*)d_out;

    float *col, *rpn, *featT, *sbuf, *sbw, *sbb, *hw, *hb, *hd, *part, *part2;
    float *props, *psc, *pbv, *psv, *rois, *pooled, *x6, *x7;
    unsigned long long *keys, *mask;
    cudaGetSymbolAddress((void**)&col, g_col);
    cudaGetSymbolAddress((void**)&rpn, g_rpn);
    cudaGetSymbolAddress((void**)&featT, g_featT);
    cudaGetSymbolAddress((void**)&sbuf, g_sb);
    cudaGetSymbolAddress((void**)&sbw, g_sbw);
    cudaGetSymbolAddress((void**)&sbb, g_sbb);
    cudaGetSymbolAddress((void**)&hw, g_hw);
    cudaGetSymbolAddress((void**)&hb, g_hb);
    cudaGetSymbolAddress((void**)&hd, g_hd);
    cudaGetSymbolAddress((void**)&part, g_part);
    cudaGetSymbolAddress((void**)&part2, g_part2);
    cudaGetSymbolAddress((void**)&props, g_props);
    cudaGetSymbolAddress((void**)&psc, g_psc);
    cudaGetSymbolAddress((void**)&keys, g_keys);
    cudaGetSymbolAddress((void**)&pbv, g_pb);
    cudaGetSymbolAddress((void**)&psv, g_ps);
    cudaGetSymbolAddress((void**)&mask, g_mask);
    cudaGetSymbolAddress((void**)&rois, g_rois);
    cudaGetSymbolAddress((void**)&pooled, g_pooled);
    cudaGetSymbolAddress((void**)&x6, g_x6);
    cudaGetSymbolAddress((void**)&x7, g_x7);

    const int MT_NP = (NP + 127) / 128;   // 19

    cudaFuncSetAttribute(mma_gemm, cudaFuncAttributeMaxDynamicSharedMemorySize, MM2_SMEM);
    cudaFuncSetAttribute(bitonic_local8k, cudaFuncAttributeMaxDynamicSharedMemorySize, 65536);
    cudaFuncSetAttribute(bitonic_tail8k, cudaFuncAttributeMaxDynamicSharedMemorySize, 65536);

    // 0. weight concats + feature transpose (input-only deps)
    concat_sb<<<(54 * 512 + 255) / 256, 256>>>(sw, sb, bw, bb, sbw, sbb);
    concat_hd<<<(160 * 4096 + 255) / 256, 256>>>(sfw, sfb, bfw, bfb, hw, hb);
    {
        dim3 gt((NP + 31) / 32, CIN / 32);
        transpose_feat<<<gt, dim3(32, 32)>>>(feat, featT);
    }

    // 1. im2col + conv1 (split-K S=4 scalar GEMM) + relu -> rpn (HWC)
    {
        int total = NP * K_CONV;
        im2col_kernel<<<(total + 255) / 256, 256>>>(feat, col);
        dim3 grid(MT_NP, 4, 4);  // Kc = 1152, 304 CTAs
        sgemm_tn<<<grid, 256>>>(col, c1w, c1b, rpn, part2, NP, CIN, K_CONV, 1);
        reduce_splits<<<(NP * CIN + 255) / 256, 256>>>(part2, c1b, rpn, NP, CIN, 4, 1);
    }
    // 2. merged score+bbox 1x1 conv (N=54)
    {
        dim3 g1(MT_NP, 1, 4);  // Kc = 128
        sgemm_tn<<<g1, 256>>>(rpn, sbw, sbb, sbuf, part2, NP, 54, CIN, 0);
        reduce_splits<<<(NP * 54 + 255) / 256, 256>>>(part2, sbb, sbuf, NP, 54, 4, 0);
    }
    // 3. proposals + sort keys
    proposal_prep<<<SORTN / 256, 256>>>(sbuf, info, props, psc, keys);
    // 4. bitonic sort (6 launches)
    bitonic_local8k<<<4, 1024, 65536>>>(keys);
    bitonic_global_pass<<<SORTN / 2 / 256, 256>>>(keys, 16384, 8192);
    bitonic_tail8k<<<4, 1024, 65536>>>(keys, 16384);
    bitonic_global_pass<<<SORTN / 2 / 256, 256>>>(keys, 32768, 16384);
    bitonic_global_pass<<<SORTN / 2 / 256, 256>>>(keys, 32768, 8192);
    bitonic_tail8k<<<4, 1024, 65536>>>(keys, 32768);
    // 5. gather top-6000
    gather_pre<<<(PRE_NMS + 255) / 256, 256>>>(keys, props, psc, pbv, psv);
    // 6. NMS: pairwise mask (upper triangle only) + block-parallel bitmap scan
    {
        dim3 gm(NWRD, NWRD);
        nms_mask_kernel<<<gm, 64>>>(pbv, mask);
        nms_scan2<<<1, 256>>>(mask, pbv, psv, rois, out + 48000);
    }
    // 7. ROI pool (HWC, channel-coalesced float2, 256 threads)
    roipool_hwc<<<POST_NMS, 256>>>(featT, rois, pooled);
    // 8. FC stack: fc6/fc7 HMMA bf16-split (ldmatrix, R11 config); heads scalar
    {
        dim3 g6(5, 32, 4);   // Kc = 6272 (196 chunks), 640 CTAs
        mma_gemm<<<g6, 256, MM2_SMEM>>>(pooled, fc6w, fc6b, x6, part, POST_NMS, 4096, K_FC6, 1);
        reduce_splits<<<(POST_NMS * 4096 + 255) / 256, 256>>>(part, fc6b, x6, POST_NMS, 4096, 4, 1);

        dim3 g7(5, 32, 2);   // Kc = 2048 (64 chunks), 320 CTAs
        mma_gemm<<<g7, 256, MM2_SMEM>>>(x6, fc7w, fc7b, x7, part, POST_NMS, 4096, 4096, 1);
        reduce_splits<<<(POST_NMS * 4096 + 255) / 256, 256>>>(part, fc7b, x7, POST_NMS, 4096, 2, 1);

        dim3 gh(3, 2, 4);    // merged heads N=160, Kc = 1024
        sgemm_tn<<<gh, 256>>>(x7, hw, hb, hd, part, POST_NMS, 160, 4096, 0);
        reduce_splits<<<(POST_NMS * 160 + 255) / 256, 256>>>(part, hb, hd, POST_NMS, 160, 4, 0);
    }
    // 9. cls softmax + box copy -> out
    heads_out<<<POST_NMS, 160>>>(hd, out);
}

// round 15
// speedup vs baseline: 1.0801x; 1.0801x over previous
#include <cuda_runtime.h>
#include <cuda_bf16.h>
#include <cstdint>

// ---------------------------------------------------------------------------
// Problem constants
// ---------------------------------------------------------------------------
#define HH 38
#define WW 63
#define NP (HH*WW)          // 2394 pixels
#define CIN 512
#define AA 9
#define NANCH (NP*AA)       // 21546
#define SORTN 32768
#define PRE_NMS 6000
#define POST_NMS 300
#define K_CONV (CIN*9)      // 4608
#define K_FC6 (512*49)      // 25088
#define NCLS 32
#define NWRD 94             // ceil(6000/64)
#define NW32 188            // ceil(6000/32)

// ---------------------------------------------------------------------------
// Static device scratch (no allocation allowed)
// ---------------------------------------------------------------------------
__device__ float g_col[NP * K_CONV];          // im2col  (~44MB)
__device__ float g_rpn[NP * CIN];             // rpn conv out, HWC
__device__ float g_featT[NP * CIN];           // transposed features (HWC)
__device__ float g_sb[NP * 54];               // merged score(18)+bbox(36) out
__device__ float g_sbw[54 * 512];             // merged conv weights
__device__ float g_sbb[54];
__device__ float g_hw[160 * 4096];            // merged head weights
__device__ float g_hb[160];
__device__ float g_hd[POST_NMS * 160];        // merged head out
__device__ float g_part[8 * 300 * 4096];      // split-K partials (max: fc6 S=7)
__device__ float g_part2[4 * NP * 512];       // split-K partials (NP-row gemms)
__device__ float g_props[NANCH * 4];
__device__ float g_psc[NANCH];
__device__ unsigned long long g_keys[SORTN];
__device__ float g_pb[PRE_NMS * 4];
__device__ float g_ps[PRE_NMS];
__device__ unsigned long long g_mask[(size_t)PRE_NMS * NWRD];  // 4.5MB
__device__ float g_rois[POST_NMS * 4];
__device__ float g_pooled[POST_NMS * K_FC6];  // (~30MB)
__device__ float g_x6[POST_NMS * 4096];
__device__ float g_x7[POST_NMS * 4096];

// 9 anchors (precomputed to match _generate_anchors incl. numpy banker's rounding)
__constant__ float c_anch[9][4] = {
    {-84.f,  -40.f,  99.f,  55.f},
    {-176.f, -88.f,  191.f, 103.f},
    {-360.f, -184.f, 375.f, 199.f},
    {-56.f,  -56.f,  71.f,  71.f},
    {-120.f, -120.f, 135.f, 135.f},
    {-248.f, -248.f, 263.f, 263.f},
    {-36.f,  -80.f,  51.f,  95.f},
    {-80.f,  -168.f, 95.f,  183.f},
    {-168.f, -344.f, 183.f, 359.f}};

__device__ __forceinline__ unsigned fkey_asc(float f) {
    unsigned u = __float_as_uint(f);
    return (u & 0x80000000u) ? ~u : (u | 0x80000000u);
}
__device__ __forceinline__ float neg_inf_f() { return __int_as_float(0xff800000); }

// ---------------------------------------------------------------------------
// Warp-MMA GEMM (bf16-split, fp32 accum): C[M,N] = A[M,K]*B[N,K]^T.
// CTA tile 64(M) x 128(N), BK=32, 8 warps of 32x32 (wm:2 x wn:4).
// ldmatrix fragment loads. A*B ~= Ahi*Bhi + Ahi*Blo + Alo*Bhi.
// (Exact R11 configuration - measured 1806us.)
// Requires: N % 128 == 0, (K/gridDim.z) % 32 == 0. Grid (mT, nT, S).
// ---------------------------------------------------------------------------
#define MPAD 40                      // bf16 elems per smem row (32 + 8 pad)
#define A_TILE (64 * MPAD * 2)       // 5120 B per A buffer (hi or lo)
#define B_TILE (128 * MPAD * 2)      // 10240 B per B buffer
#define MBUF (2 * A_TILE + 2 * B_TILE)   // 30720 B
#define MM2_SMEM (2 * MBUF)              // 61440 B

__device__ __forceinline__ void mma16816(float* c, const uint32_t* a, const uint32_t* b) {
    asm volatile(
        "mma.sync.aligned.m16n8k16.row.col.f32.bf16.bf16.f32 "
        "{%0,%1,%2,%3}, {%4,%5,%6,%7}, {%8,%9}, {%0,%1,%2,%3};"
        : "+f"(c[0]), "+f"(c[1]), "+f"(c[2]), "+f"(c[3])
        : "r"(a[0]), "r"(a[1]), "r"(a[2]), "r"(a[3]), "r"(b[0]), "r"(b[1]));
}

__device__ __forceinline__ void ldsm4(uint32_t* r, uint32_t addr) {
    asm volatile(
        "ldmatrix.sync.aligned.m8n8.x4.shared.b16 {%0,%1,%2,%3}, [%4];"
        : "=r"(r[0]), "=r"(r[1]), "=r"(r[2]), "=r"(r[3]) : "r"(addr));
}

__device__ __forceinline__ void f4_to_bf(const float4& v, uint32_t& hi0, uint32_t& hi1,
                                         uint32_t& lo0, uint32_t& lo1) {
    __nv_bfloat162 h0, h1, l0, l1;
    h0.x = __float2bfloat16(v.x); h0.y = __float2bfloat16(v.y);
    h1.x = __float2bfloat16(v.z); h1.y = __float2bfloat16(v.w);
    l0.x = __float2bfloat16(v.x - __bfloat162float(h0.x));
    l0.y = __float2bfloat16(v.y - __bfloat162float(h0.y));
    l1.x = __float2bfloat16(v.z - __bfloat162float(h1.x));
    l1.y = __float2bfloat16(v.w - __bfloat162float(h1.y));
    hi0 = *(uint32_t*)&h0; hi1 = *(uint32_t*)&h1;
    lo0 = *(uint32_t*)&l0; lo1 = *(uint32_t*)&l1;
}

__global__ void __launch_bounds__(256)
mma_gemm(const float* __restrict__ A, const float* __restrict__ B,
         const float* __restrict__ bias, float* __restrict__ C,
         float* __restrict__ part, int M, int N, int K, int relu) {
    extern __shared__ char smem[];
    const int tid = threadIdx.x;
    const int wid = tid >> 5;
    const int lane = tid & 31;

    const int S = gridDim.z;
    const int Kc = K / S;
    const int k0 = blockIdx.z * Kc;
    const int m0 = blockIdx.x * 64;
    const int n0 = blockIdx.y * 128;
    const int nChunks = Kc >> 5;

    const int wm = wid & 1;          // rows 32*wm  (0..1)
    const int wn = wid >> 1;         // cols 32*wn  (0..3)

    float acc[2][4][4];
#pragma unroll
    for (int i = 0; i < 2; i++)
#pragma unroll
        for (int j = 0; j < 4; j++)
#pragma unroll
            for (int q = 0; q < 4; q++) acc[i][j][q] = 0.f;

    // ldmatrix per-lane byte offsets within tiles
    const uint32_t smem_u = (uint32_t)__cvta_generic_to_shared(smem);
    const int r8 = lane & 7;
    const int amr = ((lane >> 3) & 1) << 3;   // A: +0/+8 rows (matrix 1,3)
    const int amc = ((lane >> 4) & 1) << 3;   // A: +0/+8 k    (matrix 2,3)
    const int bnr = ((lane >> 4) & 1) << 3;   // B: +0/+8 n within pair
    const int bkc = ((lane >> 3) & 1) << 3;   // B: +0/+8 k
    const uint32_t aLane = (uint32_t)((wm * 32 + amr + r8) * (MPAD * 2) + amc * 2);
    const uint32_t bLane = (uint32_t)((wn * 32 + bnr + r8) * (MPAD * 2) + bkc * 2);

    // loader coords
    int aRow[2], aC4[2], bRow[4], bC4[4];
#pragma unroll
    for (int q = 0; q < 2; q++) {
        int e = q * 256 + tid;
        aRow[q] = e >> 3;
        aC4[q] = (e & 7) << 2;
    }
#pragma unroll
    for (int q = 0; q < 4; q++) {
        int e = q * 256 + tid;
        bRow[q] = e >> 3;
        bC4[q] = (e & 7) << 2;
    }
    int aRowG[2];
#pragma unroll
    for (int q = 0; q < 2; q++) {
        int r = m0 + aRow[q];
        aRowG[q] = (r < M) ? r : (M - 1);
    }

    float4 ra[2], rb[4];
    auto issue_loads = [&](int it) {
        int gk = k0 + it * 32;
#pragma unroll
        for (int q = 0; q < 2; q++)
            ra[q] = *(const float4*)(A + (size_t)aRowG[q] * K + gk + aC4[q]);
#pragma unroll
        for (int q = 0; q < 4; q++)
            rb[q] = *(const float4*)(B + (size_t)(n0 + bRow[q]) * K + gk + bC4[q]);
    };
    auto cvt_store = [&](int b) {
        char* buf = smem + b * MBUF;
        char* bAhi = buf;
        char* bAlo = buf + A_TILE;
        char* bBhi = buf + 2 * A_TILE;
        char* bBlo = bBhi + B_TILE;
#pragma unroll
        for (int q = 0; q < 2; q++) {
            uint32_t h0, h1, l0, l1;
            f4_to_bf(ra[q], h0, h1, l0, l1);
            size_t off = (size_t)aRow[q] * (MPAD * 2) + aC4[q] * 2;
            *(uint2*)(bAhi + off) = make_uint2(h0, h1);
            *(uint2*)(bAlo + off) = make_uint2(l0, l1);
        }
#pragma unroll
        for (int q = 0; q < 4; q++) {
            uint32_t h0, h1, l0, l1;
            f4_to_bf(rb[q], h0, h1, l0, l1);
            size_t off = (size_t)bRow[q] * (MPAD * 2) + bC4[q] * 2;
            *(uint2*)(bBhi + off) = make_uint2(h0, h1);
            *(uint2*)(bBlo + off) = make_uint2(l0, l1);
        }
    };

    issue_loads(0);
    cvt_store(0);
    __syncthreads();

    for (int it = 0; it < nChunks; ++it) {
        const bool more = (it + 1 < nChunks);
        if (more) issue_loads(it + 1);     // LDGs in flight during MMA section

        const uint32_t base = smem_u + (it & 1) * MBUF;
        const uint32_t aHiB = base + aLane;
        const uint32_t aLoB = base + A_TILE + aLane;
        const uint32_t bHiB = base + 2 * A_TILE + bLane;
        const uint32_t bLoB = base + 2 * A_TILE + B_TILE + bLane;
#pragma unroll
        for (int ks = 0; ks < 2; ks++) {
            const uint32_t kb = (uint32_t)(ks * 16 * 2);   // byte offset of k-step
            uint32_t ah[2][4], al[2][4];
#pragma unroll
            for (int mf = 0; mf < 2; mf++) {
                uint32_t moff = (uint32_t)(mf * 16 * (MPAD * 2)) + kb;
                ldsm4(ah[mf], aHiB + moff);
                ldsm4(al[mf], aLoB + moff);
            }
            uint32_t bh[4][2], bl[4][2];
#pragma unroll
            for (int p = 0; p < 2; p++) {
                uint32_t poff = (uint32_t)(p * 16 * (MPAD * 2)) + kb;
                uint32_t t4[4];
                ldsm4(t4, bHiB + poff);
                bh[2 * p][0] = t4[0]; bh[2 * p][1] = t4[1];
                bh[2 * p + 1][0] = t4[2]; bh[2 * p + 1][1] = t4[3];
                ldsm4(t4, bLoB + poff);
                bl[2 * p][0] = t4[0]; bl[2 * p][1] = t4[1];
                bl[2 * p + 1][0] = t4[2]; bl[2 * p + 1][1] = t4[3];
            }
#pragma unroll
            for (int nf = 0; nf < 4; nf++) {
#pragma unroll
                for (int mf = 0; mf < 2; mf++) {
                    mma16816(acc[mf][nf], ah[mf], bh[nf]);
                    mma16816(acc[mf][nf], ah[mf], bl[nf]);
                    mma16816(acc[mf][nf], al[mf], bh[nf]);
                }
            }
        }
        if (more) cvt_store((it + 1) & 1); // consume LDG results after MMA cover
        __syncthreads();
    }

    // epilogue
    const int g = lane >> 2;
    const int tg = lane & 3;
#pragma unroll
    for (int mf = 0; mf < 2; mf++) {
        int row0 = m0 + wm * 32 + mf * 16 + g;
        int row1 = row0 + 8;
#pragma unroll
        for (int nf = 0; nf < 4; nf++) {
            int col = n0 + wn * 32 + nf * 8 + 2 * tg;
            if (S == 1) {
                if (row0 < M) {
                    float v0 = acc[mf][nf][0] + bias[col];
                    float v1 = acc[mf][nf][1] + bias[col + 1];
                    if (relu) { v0 = fmaxf(v0, 0.f); v1 = fmaxf(v1, 0.f); }
                    C[(size_t)row0 * N + col] = v0;
                    C[(size_t)row0 * N + col + 1] = v1;
                }
                if (row1 < M) {
                    float v2 = acc[mf][nf][2] + bias[col];
                    float v3 = acc[mf][nf][3] + bias[col + 1];
                    if (relu) { v2 = fmaxf(v2, 0.f); v3 = fmaxf(v3, 0.f); }
                    C[(size_t)row1 * N + col] = v2;
                    C[(size_t)row1 * N + col + 1] = v3;
                }
            } else {
                float* P = part + (size_t)blockIdx.z * M * N;
                if (row0 < M) {
                    P[(size_t)row0 * N + col] = acc[mf][nf][0];
                    P[(size_t)row0 * N + col + 1] = acc[mf][nf][1];
                }
                if (row1 < M) {
                    P[(size_t)row1 * N + col] = acc[mf][nf][2];
                    P[(size_t)row1 * N + col + 1] = acc[mf][nf][3];
                }
            }
        }
    }
}

// ---------------------------------------------------------------------------
// im2col for 3x3 pad 1 conv on [512,38,63]
// ---------------------------------------------------------------------------
__global__ void im2col_kernel(const float* __restrict__ feat, float* __restrict__ col) {
    int idx = blockIdx.x * blockDim.x + threadIdx.x;
    if (idx >= NP * K_CONV) return;
    int p = idx / K_CONV;
    int k = idx - p * K_CONV;
    int ic = k / 9;
    int r = k - ic * 9;
    int ky = r / 3, kx = r - ky * 3;
    int y0 = p / WW, x0 = p - y0 * WW;
    int y = y0 + ky - 1, x = x0 + kx - 1;
    float v = 0.f;
    if (y >= 0 && y < HH && x >= 0 && x < WW)
        v = feat[ic * NP + y * WW + x];
    col[idx] = v;
}

// CHW -> HWC transpose of the input features (32x32 smem tiles)
__global__ void transpose_feat(const float* __restrict__ feat, float* __restrict__ featT) {
    __shared__ float tile[32][33];
    int p0 = blockIdx.x * 32, c0 = blockIdx.y * 32;
    int p = p0 + threadIdx.x;
    int c = c0 + threadIdx.y;
    if (p < NP) tile[threadIdx.y][threadIdx.x] = feat[(size_t)c * NP + p];
    __syncthreads();
    int pw = p0 + threadIdx.y, cw = c0 + threadIdx.x;
    if (pw < NP) featT[(size_t)pw * CIN + cw] = tile[threadIdx.x][threadIdx.y];
}

// Weight concat kernels (merge small GEMMs)
__global__ void concat_sb(const float* __restrict__ sw, const float* __restrict__ sb,
                          const float* __restrict__ bw, const float* __restrict__ bb,
                          float* __restrict__ w, float* __restrict__ b) {
    int idx = blockIdx.x * blockDim.x + threadIdx.x;
    if (idx < 54 * 512) {
        int row = idx / 512, col = idx - row * 512;
        w[idx] = (row < 18) ? sw[row * 512 + col] : bw[(row - 18) * 512 + col];
    }
    if (idx < 54) b[idx] = (idx < 18) ? sb[idx] : bb[idx - 18];
}

__global__ void concat_hd(const float* __restrict__ sfw, const float* __restrict__ sfb,
                          const float* __restrict__ bfw, const float* __restrict__ bfb,
                          float* __restrict__ w, float* __restrict__ b) {
    int idx = blockIdx.x * blockDim.x + threadIdx.x;
    if (idx < 160 * 4096) {
        int row = idx / 4096, col = idx - row * 4096;
        w[idx] = (row < 32) ? sfw[row * 4096 + col] : bfw[(row - 32) * 4096 + col];
    }
    if (idx < 160) b[idx] = (idx < 32) ? sfb[idx] : bfb[idx - 32];
}

// ---------------------------------------------------------------------------
// Scalar SGEMM (conv1, merged 1x1 conv, merged heads)
// ---------------------------------------------------------------------------
__global__ void __launch_bounds__(256, 2)
sgemm_tn(const float* __restrict__ A, const float* __restrict__ B,
         const float* __restrict__ bias, float* __restrict__ C,
         float* __restrict__ part, int M, int N, int K, int relu) {
    const int S = gridDim.z;
    const int Kc = K / S;
    const int k0 = blockIdx.z * Kc;
    const int m0 = blockIdx.x * 128;
    const int n0 = blockIdx.y * 128;

    __shared__ float As[2][8][132];
    __shared__ float Bs[2][8][132];

    const int tid = threadIdx.x;
    const int lr = tid >> 1;
    const int lc = (tid & 1) << 2;

    int arow = m0 + lr; if (arow >= M) arow = M - 1;
    int brow = n0 + lr; if (brow >= N) brow = N - 1;
    const float* Ap = A + (size_t)arow * K + k0 + lc;
    const float* Bp = B + (size_t)brow * K + k0 + lc;

    const int tx = tid & 15, ty = tid >> 4;
    const int mm = ty << 3, nn = tx << 3;

    float acc[8][8];
#pragma unroll
    for (int i = 0; i < 8; i++)
#pragma unroll
        for (int j = 0; j < 8; j++) acc[i][j] = 0.f;

    const int nIter = Kc >> 3;
    float4 a4 = *(const float4*)Ap;
    float4 b4 = *(const float4*)Bp;
    As[0][lc + 0][lr] = a4.x; As[0][lc + 1][lr] = a4.y;
    As[0][lc + 2][lr] = a4.z; As[0][lc + 3][lr] = a4.w;
    Bs[0][lc + 0][lr] = b4.x; Bs[0][lc + 1][lr] = b4.y;
    Bs[0][lc + 2][lr] = b4.z; Bs[0][lc + 3][lr] = b4.w;
    __syncthreads();

    int buf = 0;
    for (int it = 0; it < nIter; ++it) {
        float4 a4n, b4n;
        const bool more = (it + 1 < nIter);
        if (more) {
            a4n = *(const float4*)(Ap + (size_t)(it + 1) * 8);
            b4n = *(const float4*)(Bp + (size_t)(it + 1) * 8);
        }
#pragma unroll
        for (int kk = 0; kk < 8; ++kk) {
            float4 a0 = *(const float4*)&As[buf][kk][mm];
            float4 a1 = *(const float4*)&As[buf][kk][mm + 4];
            float4 b0 = *(const float4*)&Bs[buf][kk][nn];
            float4 b1 = *(const float4*)&Bs[buf][kk][nn + 4];
            float ar[8] = {a0.x, a0.y, a0.z, a0.w, a1.x, a1.y, a1.z, a1.w};
            float br[8] = {b0.x, b0.y, b0.z, b0.w, b1.x, b1.y, b1.z, b1.w};
#pragma unroll
            for (int i = 0; i < 8; i++)
#pragma unroll
                for (int j = 0; j < 8; j++) acc[i][j] += ar[i] * br[j];
        }
        if (more) {
            int nb = buf ^ 1;
            As[nb][lc + 0][lr] = a4n.x; As[nb][lc + 1][lr] = a4n.y;
            As[nb][lc + 2][lr] = a4n.z; As[nb][lc + 3][lr] = a4n.w;
            Bs[nb][lc + 0][lr] = b4n.x; Bs[nb][lc + 1][lr] = b4n.y;
            Bs[nb][lc + 2][lr] = b4n.z; Bs[nb][lc + 3][lr] = b4n.w;
            __syncthreads();
            buf = nb;
        }
    }

    if (S == 1) {
#pragma unroll
        for (int i = 0; i < 8; i++) {
            int gm = m0 + mm + i;
            if (gm >= M) continue;
#pragma unroll
            for (int j = 0; j < 8; j++) {
                int gn = n0 + nn + j;
                if (gn >= N) continue;
                float v = acc[i][j] + bias[gn];
                if (relu) v = fmaxf(v, 0.f);
                C[(size_t)gm * N + gn] = v;
            }
        }
    } else {
        float* P = part + (size_t)blockIdx.z * M * N;
#pragma unroll
        for (int i = 0; i < 8; i++) {
            int gm = m0 + mm + i;
            if (gm >= M) continue;
#pragma unroll
            for (int j = 0; j < 8; j++) {
                int gn = n0 + nn + j;
                if (gn >= N) continue;
                P[(size_t)gm * N + gn] = acc[i][j];
            }
        }
    }
}

// Deterministic split-K reduction: C = sum_z part[z] + bias (+relu)
__global__ void reduce_splits(const float* __restrict__ part, const float* __restrict__ bias,
                              float* __restrict__ C, int M, int N, int S, int relu) {
    int idx = blockIdx.x * blockDim.x + threadIdx.x;
    int total = M * N;
    if (idx >= total) return;
    float s = 0.f;
    for (int z = 0; z < S; z++) s += part[(size_t)z * total + idx];
    s += bias[idx % N];
    if (relu) s = fmaxf(s, 0.f);
    C[idx] = s;
}

// ---------------------------------------------------------------------------
// Proposal prep: reads merged sb [NP][54] (cols 0..17 score, 18..53 deltas)
// ---------------------------------------------------------------------------
__global__ void proposal_prep(const float* __restrict__ sbuf,
                              const float* __restrict__ info,
                              float* __restrict__ props, float* __restrict__ psc,
                              unsigned long long* __restrict__ keys) {
    int i = blockIdx.x * blockDim.x + threadIdx.x;
    if (i >= SORTN) return;
    if (i >= NANCH) { keys[i] = ~0ull; return; }
    int p = i / AA, a = i - p * AA;
    int hy = p / WW, wx = p - hy * WW;
    float shx = wx * 16.f, shy = hy * 16.f;
    float ax1 = c_anch[a][0] + shx, ay1 = c_anch[a][1] + shy;
    float ax2 = c_anch[a][2] + shx, ay2 = c_anch[a][3] + shy;
    float aw = ax2 - ax1 + 1.f, ah = ay2 - ay1 + 1.f;
    float cx = ax1 + 0.5f * aw, cy = ay1 + 0.5f * ah;
    const float* row = sbuf + (size_t)p * 54;
    const float* d = row + 18 + a * 4;
    float pcx = d[0] * aw + cx;
    float pcy = d[1] * ah + cy;
    float pw_ = expf(d[2]) * aw;
    float ph_ = expf(d[3]) * ah;
    float imh = info[0], imw = info[1], sc = info[2];
    float x1 = fminf(fmaxf(pcx - 0.5f * pw_, 0.f), imw - 1.f);
    float y1 = fminf(fmaxf(pcy - 0.5f * ph_, 0.f), imh - 1.f);
    float x2 = fminf(fmaxf(pcx + 0.5f * pw_, 0.f), imw - 1.f);
    float y2 = fminf(fmaxf(pcy + 0.5f * ph_, 0.f), imh - 1.f);
    bool ok = ((x2 - x1 + 1.f) >= 16.f * sc) && ((y2 - y1 + 1.f) >= 16.f * sc);
    float s0 = row[a];
    float s1 = row[a + 9];
    float m = fmaxf(s0, s1);
    float e0 = expf(s0 - m), e1 = expf(s1 - m);
    float prob = e1 / (e0 + e1);
    float score = ok ? prob : neg_inf_f();
    props[i * 4 + 0] = x1; props[i * 4 + 1] = y1;
    props[i * 4 + 2] = x2; props[i * 4 + 3] = y2;
    psc[i] = score;
    unsigned fk = fkey_asc(score);
    keys[i] = ((unsigned long long)(~fk) << 32) | (unsigned)i;
}

// ---------------------------------------------------------------------------
// Bitonic sort on 32768 u64 keys: 8192-wide local blocks + global passes.
// ---------------------------------------------------------------------------
__global__ void bitonic_local8k(unsigned long long* keys) {
    extern __shared__ unsigned long long s8[];
    int base = blockIdx.x * 8192, t = threadIdx.x;
#pragma unroll
    for (int q = 0; q < 8; q++) s8[t + q * 1024] = keys[base + t + q * 1024];
    __syncthreads();
    for (int k = 2; k <= 8192; k <<= 1) {
        for (int j = k >> 1; j > 0; j >>= 1) {
#pragma unroll
            for (int q = 0; q < 4; q++) {
                int p = t + q * 1024;
                int i = ((p & ~(j - 1)) << 1) | (p & (j - 1));
                int l = i + j;
                bool up = (((base + i) & k) == 0);
                unsigned long long a = s8[i], b = s8[l];
                if (up ? (a > b) : (a < b)) { s8[i] = b; s8[l] = a; }
            }
            __syncthreads();
        }
    }
#pragma unroll
    for (int q = 0; q < 8; q++) keys[base + t + q * 1024] = s8[t + q * 1024];
}

__global__ void bitonic_global_pass(unsigned long long* keys, int k, int j) {
    int p = blockIdx.x * blockDim.x + threadIdx.x;
    int i = ((p & ~(j - 1)) << 1) | (p & (j - 1));
    int l = i + j;
    bool up = ((i & k) == 0);
    unsigned long long a = keys[i], b = keys[l];
    if (up ? (a > b) : (a < b)) { keys[i] = b; keys[l] = a; }
}

__global__ void bitonic_tail8k(unsigned long long* keys, int k) {
    extern __shared__ unsigned long long s8[];
    int base = blockIdx.x * 8192, t = threadIdx.x;
#pragma unroll
    for (int q = 0; q < 8; q++) s8[t + q * 1024] = keys[base + t + q * 1024];
    __syncthreads();
    for (int j = 4096; j > 0; j >>= 1) {
#pragma unroll
        for (int q = 0; q < 4; q++) {
            int p = t + q * 1024;
            int i = ((p & ~(j - 1)) << 1) | (p & (j - 1));
            int l = i + j;
            bool up = (((base + i) & k) == 0);
            unsigned long long a = s8[i], b = s8[l];
            if (up ? (a > b) : (a < b)) { s8[i] = b; s8[l] = a; }
        }
        __syncthreads();
    }
#pragma unroll
    for (int q = 0; q < 8; q++) keys[base + t + q * 1024] = s8[t + q * 1024];
}

__global__ void gather_pre(const unsigned long long* __restrict__ keys,
                           const float* __restrict__ props, const float* __restrict__ psc,
                           float* __restrict__ pb, float* __restrict__ ps) {
    int i = blockIdx.x * blockDim.x + threadIdx.x;
    if (i >= PRE_NMS) return;
    unsigned idx = (unsigned)(keys[i] & 0xFFFFFFFFull);
    pb[i * 4 + 0] = props[idx * 4 + 0];
    pb[i * 4 + 1] = props[idx * 4 + 1];
    pb[i * 4 + 2] = props[idx * 4 + 2];
    pb[i * 4 + 3] = props[idx * 4 + 3];
    ps[i] = psc[idx];
}

// ---------------------------------------------------------------------------
// NMS stage 1: pairwise suppression bitmask (upper triangle: i suppresses j>i).
// Lower-triangle blocks skipped: those words are never non-zero and g_mask is
// zero-initialized (condition is data-independent), so reads stay correct.
// ---------------------------------------------------------------------------
__global__ void nms_mask_kernel(const float* __restrict__ pb,
                                unsigned long long* __restrict__ mask) {
    int jb = blockIdx.x;
    int ib = blockIdx.y;
    if (jb * 64 + 63 <= ib * 64) return;   // whole block lower-triangle
    int t = threadIdx.x;
    __shared__ float cb[64][5];
    int j0 = jb * 64;
    if (j0 + t < PRE_NMS) {
        float x1 = pb[(j0 + t) * 4 + 0];
        float y1 = pb[(j0 + t) * 4 + 1];
        float x2 = pb[(j0 + t) * 4 + 2];
        float y2 = pb[(j0 + t) * 4 + 3];
        cb[t][0] = x1; cb[t][1] = y1; cb[t][2] = x2; cb[t][3] = y2;
        cb[t][4] = (x2 - x1 + 1.f) * (y2 - y1 + 1.f);
    }
    __syncthreads();
    int i = ib * 64 + t;
    if (i >= PRE_NMS) return;
    unsigned long long w = 0ull;
    if (j0 + 63 > i) {
        float bx1 = pb[i * 4 + 0], by1 = pb[i * 4 + 1];
        float bx2 = pb[i * 4 + 2], by2 = pb[i * 4 + 3];
        float ba = (bx2 - bx1 + 1.f) * (by2 - by1 + 1.f);
        int cols = min(64, PRE_NMS - j0);
        for (int tt = 0; tt < cols; tt++) {
            int j = j0 + tt;
            if (j <= i) continue;
            float xx1 = fmaxf(bx1, cb[tt][0]);
            float yy1 = fmaxf(by1, cb[tt][1]);
            float xx2 = fminf(bx2, cb[tt][2]);
            float yy2 = fminf(by2, cb[tt][3]);
            float inter = fmaxf(xx2 - xx1 + 1.f, 0.f) * fmaxf(yy2 - yy1 + 1.f, 0.f);
            float iou = inter / (ba + cb[tt][4] - inter);
            if (iou > 0.7f) w |= (1ull << tt);
        }
    }
    mask[(size_t)i * NWRD + jb] = w;
}

// ---------------------------------------------------------------------------
// NMS stage 2: block-parallel greedy scan over an alive bitmap.
// ---------------------------------------------------------------------------
__global__ void nms_scan2(const unsigned long long* __restrict__ mask,
                          const float* __restrict__ pb,
                          const float* __restrict__ ps,
                          float* __restrict__ rois, float* __restrict__ out_rois) {
    __shared__ unsigned alive[NW32];
    __shared__ int wmin[8];
    __shared__ int s_best, s_kept;
    int t = threadIdx.x;
    int lane = t & 31, wid = t >> 5;

    for (int w = wid; w < NW32; w += 8) {
        int c = w * 32 + lane;
        bool fin = (c < PRE_NMS) && (ps[c] > -3.0e38f);
        unsigned m = __ballot_sync(0xFFFFFFFFu, fin);
        if (lane == 0) alive[w] = m;
    }
    if (t == 0) s_kept = 0;
    __syncthreads();

    for (int r = 0; r < POST_NMS; r++) {
        int cand = 0x7FFFFFFF;
        if (t < NW32) {
            unsigned w = alive[t];
            if (w) cand = t * 32 + __ffs(w) - 1;
        }
#pragma unroll
        for (int o = 16; o; o >>= 1) cand = min(cand, __shfl_xor_sync(0xFFFFFFFFu, cand, o));
        if (lane == 0) wmin[wid] = cand;
        __syncthreads();
        if (t == 0) {
            int b = wmin[0];
#pragma unroll
            for (int q = 1; q < 8; q++) b = min(b, wmin[q]);
            s_best = b;
        }
        __syncthreads();
        int i = s_best;
        if (i == 0x7FFFFFFF) break;
        if (t == 0) {
            float x1 = pb[i * 4 + 0], y1 = pb[i * 4 + 1];
            float x2 = pb[i * 4 + 2], y2 = pb[i * 4 + 3];
            rois[r * 4 + 0] = x1; rois[r * 4 + 1] = y1;
            rois[r * 4 + 2] = x2; rois[r * 4 + 3] = y2;
            out_rois[r * 4 + 0] = x1; out_rois[r * 4 + 1] = y1;
            out_rois[r * 4 + 2] = x2; out_rois[r * 4 + 3] = y2;
            s_kept = r + 1;
        }
        if (t < NW32) {
            const unsigned* row = (const unsigned*)(mask + (size_t)i * NWRD);
            unsigned a = alive[t] & ~row[t];
            if (t == (i >> 5)) a &= ~(1u << (i & 31));
            alive[t] = a;
        }
        __syncthreads();
    }
    __syncthreads();
    if (t == 0) {
        int kept = s_kept;
        float x1 = pb[0], y1 = pb[1], x2 = pb[2], y2 = pb[3];
        for (int r = kept; r < POST_NMS; r++) {
            rois[r * 4 + 0] = x1; rois[r * 4 + 1] = y1;
            rois[r * 4 + 2] = x2; rois[r * 4 + 3] = y2;
            out_rois[r * 4 + 0] = x1; out_rois[r * 4 + 1] = y1;
            out_rois[r * 4 + 2] = x2; out_rois[r * 4 + 3] = y2;
        }
    }
}

// ---------------------------------------------------------------------------
// ROI max-pool 7x7, HWC layout: block per roi, 128 threads x 4 channels each.
// ---------------------------------------------------------------------------
__global__ void __launch_bounds__(128)
roipool_hwc(const float* __restrict__ featT, const float* __restrict__ rois,
            float* __restrict__ pooled) {
    int r = blockIdx.x;
    int t = threadIdx.x;
    __shared__ int hs[7], he[7], ws_[7], we[7];
    if (t == 0) {
        float x1 = rois[r * 4], y1 = rois[r * 4 + 1], x2 = rois[r * 4 + 2], y2 = rois[r * 4 + 3];
        float rsw = rintf(x1 * 0.0625f), rsh = rintf(y1 * 0.0625f);
        float rew = rintf(x2 * 0.0625f), reh = rintf(y2 * 0.0625f);
        float bw = fmaxf(rew - rsw + 1.f, 1.f) * (1.f / 7.f);
        float bh = fmaxf(reh - rsh + 1.f, 1.f) * (1.f / 7.f);
        for (int p = 0; p < 7; p++) {
            float fp = (float)p;
            hs[p] = (int)fminf(fmaxf(floorf(fp * bh) + rsh, 0.f), (float)HH);
            he[p] = (int)fminf(fmaxf(ceilf((fp + 1.f) * bh) + rsh, 0.f), (float)HH);
            ws_[p] = (int)fminf(fmaxf(floorf(fp * bw) + rsw, 0.f), (float)WW);
            we[p] = (int)fminf(fmaxf(ceilf((fp + 1.f) * bw) + rsw, 0.f), (float)WW);
        }
    }
    __syncthreads();
    const float4* fT = (const float4*)featT;    // [pix][128] float4
    float* dst = pooled + (size_t)r * K_FC6;
    int c = 4 * t;
#pragma unroll 1
    for (int bin = 0; bin < 49; bin++) {
        int ph = bin / 7, pw = bin - ph * 7;
        float4 m = make_float4(-1e30f, -1e30f, -1e30f, -1e30f);
        for (int y = hs[ph]; y < he[ph]; y++) {
            const float4* rowp = fT + (size_t)(y * WW) * 128 + t;
            for (int x = ws_[pw]; x < we[pw]; x++) {
                float4 v = rowp[(size_t)x * 128];
                m.x = fmaxf(m.x, v.x);
                m.y = fmaxf(m.y, v.y);
                m.z = fmaxf(m.z, v.z);
                m.w = fmaxf(m.w, v.w);
            }
        }
        dst[(c + 0) * 49 + bin] = (m.x < -1e29f) ? 0.f : m.x;
        dst[(c + 1) * 49 + bin] = (m.y < -1e29f) ? 0.f : m.y;
        dst[(c + 2) * 49 + bin] = (m.z < -1e29f) ? 0.f : m.z;
        dst[(c + 3) * 49 + bin] = (m.w < -1e29f) ? 0.f : m.w;
    }
}

// ---------------------------------------------------------------------------
// Heads output: softmax over 32 classes (warp 0) + box copy (threads 32..159)
// ---------------------------------------------------------------------------
__global__ void heads_out(const float* __restrict__ hd, float* __restrict__ out) {
    int r = blockIdx.x;
    int t = threadIdx.x;
    if (t < 32) {
        float v = hd[r * 160 + t];
        float m = v;
#pragma unroll
        for (int o = 16; o; o >>= 1) m = fmaxf(m, __shfl_xor_sync(0xFFFFFFFFu, m, o));
        float e = expf(v - m);
        float s = e;
#pragma unroll
        for (int o = 16; o; o >>= 1) s += __shfl_xor_sync(0xFFFFFFFFu, s, o);
        out[r * NCLS + t] = e / s;
    } else {
        out[9600 + r * 128 + (t - 32)] = hd[r * 160 + t];
    }
}

// ---------------------------------------------------------------------------
// Launch
// ---------------------------------------------------------------------------
extern "C" void kernel_launch(void* const* d_in, const int* in_sizes, int n_in,
                              void* d_out, int out_size) {
    const float* feat  = (const float*)d_in[0];
    const float* info  = (const float*)d_in[1];
    const float* c1w   = (const float*)d_in[2];
    const float* c1b   = (const float*)d_in[3];
    const float* sw    = (const float*)d_in[4];
    const float* sb    = (const float*)d_in[5];
    const float* bw    = (const float*)d_in[6];
    const float* bb    = (const float*)d_in[7];
    const float* fc6w  = (const float*)d_in[8];
    const float* fc6b  = (const float*)d_in[9];
    const float* fc7w  = (const float*)d_in[10];
    const float* fc7b  = (const float*)d_in[11];
    const float* sfw   = (const float*)d_in[12];
    const float* sfb   = (const float*)d_in[13];
    const float* bfw   = (const float*)d_in[14];
    const float* bfb   = (const float*)d_in[15];
    float* out = (float*)d_out;

    float *col, *rpn, *featT, *sbuf, *sbw, *sbb, *hw, *hb, *hd, *part, *part2;
    float *props, *psc, *pbv, *psv, *rois, *pooled, *x6, *x7;
    unsigned long long *keys, *mask;
    cudaGetSymbolAddress((void**)&col, g_col);
    cudaGetSymbolAddress((void**)&rpn, g_rpn);
    cudaGetSymbolAddress((void**)&featT, g_featT);
    cudaGetSymbolAddress((void**)&sbuf, g_sb);
    cudaGetSymbolAddress((void**)&sbw, g_sbw);
    cudaGetSymbolAddress((void**)&sbb, g_sbb);
    cudaGetSymbolAddress((void**)&hw, g_hw);
    cudaGetSymbolAddress((void**)&hb, g_hb);
    cudaGetSymbolAddress((void**)&hd, g_hd);
    cudaGetSymbolAddress((void**)&part, g_part);
    cudaGetSymbolAddress((void**)&part2, g_part2);
    cudaGetSymbolAddress((void**)&props, g_props);
    cudaGetSymbolAddress((void**)&psc, g_psc);
    cudaGetSymbolAddress((void**)&keys, g_keys);
    cudaGetSymbolAddress((void**)&pbv, g_pb);
    cudaGetSymbolAddress((void**)&psv, g_ps);
    cudaGetSymbolAddress((void**)&mask, g_mask);
    cudaGetSymbolAddress((void**)&rois, g_rois);
    cudaGetSymbolAddress((void**)&pooled, g_pooled);
    cudaGetSymbolAddress((void**)&x6, g_x6);
    cudaGetSymbolAddress((void**)&x7, g_x7);

    const int MT_NP = (NP + 127) / 128;   // 19

    cudaFuncSetAttribute(mma_gemm, cudaFuncAttributeMaxDynamicSharedMemorySize, MM2_SMEM);
    cudaFuncSetAttribute(bitonic_local8k, cudaFuncAttributeMaxDynamicSharedMemorySize, 65536);
    cudaFuncSetAttribute(bitonic_tail8k, cudaFuncAttributeMaxDynamicSharedMemorySize, 65536);

    // 0. weight concats + feature transpose (input-only deps)
    concat_sb<<<(54 * 512 + 255) / 256, 256>>>(sw, sb, bw, bb, sbw, sbb);
    concat_hd<<<(160 * 4096 + 255) / 256, 256>>>(sfw, sfb, bfw, bfb, hw, hb);
    {
        dim3 gt((NP + 31) / 32, CIN / 32);
        transpose_feat<<<gt, dim3(32, 32)>>>(feat, featT);
    }

    // 1. im2col + conv1 (split-K S=4 scalar GEMM) + relu -> rpn (HWC)
    {
        int total = NP * K_CONV;
        im2col_kernel<<<(total + 255) / 256, 256>>>(feat, col);
        dim3 grid(MT_NP, 4, 4);  // Kc = 1152, 304 CTAs
        sgemm_tn<<<grid, 256>>>(col, c1w, c1b, rpn, part2, NP, CIN, K_CONV, 1);
        reduce_splits<<<(NP * CIN + 255) / 256, 256>>>(part2, c1b, rpn, NP, CIN, 4, 1);
    }
    // 2. merged score+bbox 1x1 conv (N=54)
    {
        dim3 g1(MT_NP, 1, 4);  // Kc = 128
        sgemm_tn<<<g1, 256>>>(rpn, sbw, sbb, sbuf, part2, NP, 54, CIN, 0);
        reduce_splits<<<(NP * 54 + 255) / 256, 256>>>(part2, sbb, sbuf, NP, 54, 4, 0);
    }
    // 3. proposals + sort keys
    proposal_prep<<<SORTN / 256, 256>>>(sbuf, info, props, psc, keys);
    // 4. bitonic sort (6 launches)
    bitonic_local8k<<<4, 1024, 65536>>>(keys);
    bitonic_global_pass<<<SORTN / 2 / 256, 256>>>(keys, 16384, 8192);
    bitonic_tail8k<<<4, 1024, 65536>>>(keys, 16384);
    bitonic_global_pass<<<SORTN / 2 / 256, 256>>>(keys, 32768, 16384);
    bitonic_global_pass<<<SORTN / 2 / 256, 256>>>(keys, 32768, 8192);
    bitonic_tail8k<<<4, 1024, 65536>>>(keys, 32768);
    // 5. gather top-6000
    gather_pre<<<(PRE_NMS + 255) / 256, 256>>>(keys, props, psc, pbv, psv);
    // 6. NMS: pairwise mask (upper triangle only) + block-parallel bitmap scan
    {
        dim3 gm(NWRD, NWRD);
        nms_mask_kernel<<<gm, 64>>>(pbv, mask);
        nms_scan2<<<1, 256>>>(mask, pbv, psv, rois, out + 48000);
    }
    // 7. ROI pool (HWC, channel-coalesced float4, 128 threads — R11 config)
    roipool_hwc<<<POST_NMS, 128>>>(featT, rois, pooled);
    // 8. FC stack: fc6/fc7 HMMA bf16-split (ldmatrix); wave-balanced split-K
    {
        dim3 g6(5, 32, 7);   // Kc = 3584 (112 chunks), 1120 CTAs (3.78 waves @296)
        mma_gemm<<<g6, 256, MM2_SMEM>>>(pooled, fc6w, fc6b, x6, part, POST_NMS, 4096, K_FC6, 1);
        reduce_splits<<<(POST_NMS * 4096 + 255) / 256, 256>>>(part, fc6b, x6, POST_NMS, 4096, 7, 1);

        dim3 g7(5, 32, 4);   // Kc = 1024 (32 chunks), 640 CTAs (2.16 waves)
        mma_gemm<<<g7, 256, MM2_SMEM>>>(x6, fc7w, fc7b, x7, part, POST_NMS, 4096, 4096, 1);
        reduce_splits<<<(POST_NMS * 4096 + 255) / 256, 256>>>(part, fc7b, x7, POST_NMS, 4096, 4, 1);

        dim3 gh(3, 2, 4);    // merged heads N=160, Kc = 1024
        sgemm_tn<<<gh, 256>>>(x7, hw, hb, hd, part, POST_NMS, 160, 4096, 0);
        reduce_splits<<<(POST_NMS * 160 + 255) / 256, 256>>>(part, hb, hd, POST_NMS, 160, 4, 0);
    }
    // 9. cls softmax + box copy -> out
    heads_out<<<POST_NMS, 160>>>(hd, out);
}

// round 16
// speedup vs baseline: 1.1378x; 1.0534x over previous
#include <cuda_runtime.h>
#include <cuda_bf16.h>
#include <cstdint>

// ---------------------------------------------------------------------------
// Problem constants
// ---------------------------------------------------------------------------
#define HH 38
#define WW 63
#define NP (HH*WW)          // 2394 pixels
#define CIN 512
#define AA 9
#define NANCH (NP*AA)       // 21546
#define SORTN 32768
#define PRE_NMS 6000
#define POST_NMS 300
#define K_CONV (CIN*9)      // 4608
#define K_FC6 (512*49)      // 25088
#define NCLS 32
#define NWRD 94             // ceil(6000/64)
#define NW32 188            // ceil(6000/32)

// ---------------------------------------------------------------------------
// Static device scratch (no allocation allowed)
// ---------------------------------------------------------------------------
__device__ float g_col[NP * K_CONV];          // im2col  (~44MB)
__device__ float g_rpn[NP * CIN];             // rpn conv out, HWC
__device__ float g_featT[NP * CIN];           // transposed features (HWC)
__device__ float g_sb[NP * 54];               // merged score(18)+bbox(36) out
__device__ float g_sbw[54 * 512];             // merged conv weights
__device__ float g_sbb[54];
__device__ float g_hw[160 * 4096];            // merged head weights
__device__ float g_hb[160];
__device__ float g_hd[POST_NMS * 160];        // merged head out
__device__ float g_part[8 * 300 * 4096];      // split-K partials (max: fc6 S=7 / fc7 S=8)
__device__ float g_part2[4 * NP * 512];       // split-K partials (NP-row gemms)
__device__ float g_props[NANCH * 4];
__device__ float g_psc[NANCH];
__device__ unsigned long long g_keys[SORTN];
__device__ float g_pb[PRE_NMS * 4];
__device__ float g_ps[PRE_NMS];
__device__ unsigned long long g_mask[(size_t)PRE_NMS * NWRD];  // 4.5MB
__device__ float g_rois[POST_NMS * 4];
__device__ float g_pooled[POST_NMS * K_FC6];  // (~30MB)
__device__ float g_x6[POST_NMS * 4096];
__device__ float g_x7[POST_NMS * 4096];

// 9 anchors (precomputed to match _generate_anchors incl. numpy banker's rounding)
__constant__ float c_anch[9][4] = {
    {-84.f,  -40.f,  99.f,  55.f},
    {-176.f, -88.f,  191.f, 103.f},
    {-360.f, -184.f, 375.f, 199.f},
    {-56.f,  -56.f,  71.f,  71.f},
    {-120.f, -120.f, 135.f, 135.f},
    {-248.f, -248.f, 263.f, 263.f},
    {-36.f,  -80.f,  51.f,  95.f},
    {-80.f,  -168.f, 95.f,  183.f},
    {-168.f, -344.f, 183.f, 359.f}};

__device__ __forceinline__ unsigned fkey_asc(float f) {
    unsigned u = __float_as_uint(f);
    return (u & 0x80000000u) ? ~u : (u | 0x80000000u);
}
__device__ __forceinline__ float neg_inf_f() { return __int_as_float(0xff800000); }

// ---------------------------------------------------------------------------
// Warp-MMA GEMM (bf16-split, fp32 accum): C[M,N] = A[M,K]*B[N,K]^T.
// CTA tile 64(M) x 128(N), BK=32, 8 warps of 32x32 (wm:2 x wn:4).
// ldmatrix fragment loads. A*B ~= Ahi*Bhi + Ahi*Blo + Alo*Bhi.
// (Exact R11/R15 configuration.)
// Requires: N % 128 == 0, (K/gridDim.z) % 32 == 0. Grid (mT, nT, S).
// ---------------------------------------------------------------------------
#define MPAD 40                      // bf16 elems per smem row (32 + 8 pad)
#define A_TILE (64 * MPAD * 2)       // 5120 B per A buffer (hi or lo)
#define B_TILE (128 * MPAD * 2)      // 10240 B per B buffer
#define MBUF (2 * A_TILE + 2 * B_TILE)   // 30720 B
#define MM2_SMEM (2 * MBUF)              // 61440 B

__device__ __forceinline__ void mma16816(float* c, const uint32_t* a, const uint32_t* b) {
    asm volatile(
        "mma.sync.aligned.m16n8k16.row.col.f32.bf16.bf16.f32 "
        "{%0,%1,%2,%3}, {%4,%5,%6,%7}, {%8,%9}, {%0,%1,%2,%3};"
        : "+f"(c[0]), "+f"(c[1]), "+f"(c[2]), "+f"(c[3])
        : "r"(a[0]), "r"(a[1]), "r"(a[2]), "r"(a[3]), "r"(b[0]), "r"(b[1]));
}

__device__ __forceinline__ void ldsm4(uint32_t* r, uint32_t addr) {
    asm volatile(
        "ldmatrix.sync.aligned.m8n8.x4.shared.b16 {%0,%1,%2,%3}, [%4];"
        : "=r"(r[0]), "=r"(r[1]), "=r"(r[2]), "=r"(r[3]) : "r"(addr));
}

__device__ __forceinline__ void f4_to_bf(const float4& v, uint32_t& hi0, uint32_t& hi1,
                                         uint32_t& lo0, uint32_t& lo1) {
    __nv_bfloat162 h0, h1, l0, l1;
    h0.x = __float2bfloat16(v.x); h0.y = __float2bfloat16(v.y);
    h1.x = __float2bfloat16(v.z); h1.y = __float2bfloat16(v.w);
    l0.x = __float2bfloat16(v.x - __bfloat162float(h0.x));
    l0.y = __float2bfloat16(v.y - __bfloat162float(h0.y));
    l1.x = __float2bfloat16(v.z - __bfloat162float(h1.x));
    l1.y = __float2bfloat16(v.w - __bfloat162float(h1.y));
    hi0 = *(uint32_t*)&h0; hi1 = *(uint32_t*)&h1;
    lo0 = *(uint32_t*)&l0; lo1 = *(uint32_t*)&l1;
}

__global__ void __launch_bounds__(256)
mma_gemm(const float* __restrict__ A, const float* __restrict__ B,
         const float* __restrict__ bias, float* __restrict__ C,
         float* __restrict__ part, int M, int N, int K, int relu) {
    extern __shared__ char smem[];
    const int tid = threadIdx.x;
    const int wid = tid >> 5;
    const int lane = tid & 31;

    const int S = gridDim.z;
    const int Kc = K / S;
    const int k0 = blockIdx.z * Kc;
    const int m0 = blockIdx.x * 64;
    const int n0 = blockIdx.y * 128;
    const int nChunks = Kc >> 5;

    const int wm = wid & 1;          // rows 32*wm  (0..1)
    const int wn = wid >> 1;         // cols 32*wn  (0..3)

    float acc[2][4][4];
#pragma unroll
    for (int i = 0; i < 2; i++)
#pragma unroll
        for (int j = 0; j < 4; j++)
#pragma unroll
            for (int q = 0; q < 4; q++) acc[i][j][q] = 0.f;

    // ldmatrix per-lane byte offsets within tiles
    const uint32_t smem_u = (uint32_t)__cvta_generic_to_shared(smem);
    const int r8 = lane & 7;
    const int amr = ((lane >> 3) & 1) << 3;   // A: +0/+8 rows (matrix 1,3)
    const int amc = ((lane >> 4) & 1) << 3;   // A: +0/+8 k    (matrix 2,3)
    const int bnr = ((lane >> 4) & 1) << 3;   // B: +0/+8 n within pair
    const int bkc = ((lane >> 3) & 1) << 3;   // B: +0/+8 k
    const uint32_t aLane = (uint32_t)((wm * 32 + amr + r8) * (MPAD * 2) + amc * 2);
    const uint32_t bLane = (uint32_t)((wn * 32 + bnr + r8) * (MPAD * 2) + bkc * 2);

    // loader coords
    int aRow[2], aC4[2], bRow[4], bC4[4];
#pragma unroll
    for (int q = 0; q < 2; q++) {
        int e = q * 256 + tid;
        aRow[q] = e >> 3;
        aC4[q] = (e & 7) << 2;
    }
#pragma unroll
    for (int q = 0; q < 4; q++) {
        int e = q * 256 + tid;
        bRow[q] = e >> 3;
        bC4[q] = (e & 7) << 2;
    }
    int aRowG[2];
#pragma unroll
    for (int q = 0; q < 2; q++) {
        int r = m0 + aRow[q];
        aRowG[q] = (r < M) ? r : (M - 1);
    }

    float4 ra[2], rb[4];
    auto issue_loads = [&](int it) {
        int gk = k0 + it * 32;
#pragma unroll
        for (int q = 0; q < 2; q++)
            ra[q] = *(const float4*)(A + (size_t)aRowG[q] * K + gk + aC4[q]);
#pragma unroll
        for (int q = 0; q < 4; q++)
            rb[q] = *(const float4*)(B + (size_t)(n0 + bRow[q]) * K + gk + bC4[q]);
    };
    auto cvt_store = [&](int b) {
        char* buf = smem + b * MBUF;
        char* bAhi = buf;
        char* bAlo = buf + A_TILE;
        char* bBhi = buf + 2 * A_TILE;
        char* bBlo = bBhi + B_TILE;
#pragma unroll
        for (int q = 0; q < 2; q++) {
            uint32_t h0, h1, l0, l1;
            f4_to_bf(ra[q], h0, h1, l0, l1);
            size_t off = (size_t)aRow[q] * (MPAD * 2) + aC4[q] * 2;
            *(uint2*)(bAhi + off) = make_uint2(h0, h1);
            *(uint2*)(bAlo + off) = make_uint2(l0, l1);
        }
#pragma unroll
        for (int q = 0; q < 4; q++) {
            uint32_t h0, h1, l0, l1;
            f4_to_bf(rb[q], h0, h1, l0, l1);
            size_t off = (size_t)bRow[q] * (MPAD * 2) + bC4[q] * 2;
            *(uint2*)(bBhi + off) = make_uint2(h0, h1);
            *(uint2*)(bBlo + off) = make_uint2(l0, l1);
        }
    };

    issue_loads(0);
    cvt_store(0);
    __syncthreads();

    for (int it = 0; it < nChunks; ++it) {
        const bool more = (it + 1 < nChunks);
        if (more) issue_loads(it + 1);     // LDGs in flight during MMA section

        const uint32_t base = smem_u + (it & 1) * MBUF;
        const uint32_t aHiB = base + aLane;
        const uint32_t aLoB = base + A_TILE + aLane;
        const uint32_t bHiB = base + 2 * A_TILE + bLane;
        const uint32_t bLoB = base + 2 * A_TILE + B_TILE + bLane;
#pragma unroll
        for (int ks = 0; ks < 2; ks++) {
            const uint32_t kb = (uint32_t)(ks * 16 * 2);   // byte offset of k-step
            uint32_t ah[2][4], al[2][4];
#pragma unroll
            for (int mf = 0; mf < 2; mf++) {
                uint32_t moff = (uint32_t)(mf * 16 * (MPAD * 2)) + kb;
                ldsm4(ah[mf], aHiB + moff);
                ldsm4(al[mf], aLoB + moff);
            }
            uint32_t bh[4][2], bl[4][2];
#pragma unroll
            for (int p = 0; p < 2; p++) {
                uint32_t poff = (uint32_t)(p * 16 * (MPAD * 2)) + kb;
                uint32_t t4[4];
                ldsm4(t4, bHiB + poff);
                bh[2 * p][0] = t4[0]; bh[2 * p][1] = t4[1];
                bh[2 * p + 1][0] = t4[2]; bh[2 * p + 1][1] = t4[3];
                ldsm4(t4, bLoB + poff);
                bl[2 * p][0] = t4[0]; bl[2 * p][1] = t4[1];
                bl[2 * p + 1][0] = t4[2]; bl[2 * p + 1][1] = t4[3];
            }
#pragma unroll
            for (int nf = 0; nf < 4; nf++) {
#pragma unroll
                for (int mf = 0; mf < 2; mf++) {
                    mma16816(acc[mf][nf], ah[mf], bh[nf]);
                    mma16816(acc[mf][nf], ah[mf], bl[nf]);
                    mma16816(acc[mf][nf], al[mf], bh[nf]);
                }
            }
        }
        if (more) cvt_store((it + 1) & 1); // consume LDG results after MMA cover
        __syncthreads();
    }

    // epilogue
    const int g = lane >> 2;
    const int tg = lane & 3;
#pragma unroll
    for (int mf = 0; mf < 2; mf++) {
        int row0 = m0 + wm * 32 + mf * 16 + g;
        int row1 = row0 + 8;
#pragma unroll
        for (int nf = 0; nf < 4; nf++) {
            int col = n0 + wn * 32 + nf * 8 + 2 * tg;
            if (S == 1) {
                if (row0 < M) {
                    float v0 = acc[mf][nf][0] + bias[col];
                    float v1 = acc[mf][nf][1] + bias[col + 1];
                    if (relu) { v0 = fmaxf(v0, 0.f); v1 = fmaxf(v1, 0.f); }
                    C[(size_t)row0 * N + col] = v0;
                    C[(size_t)row0 * N + col + 1] = v1;
                }
                if (row1 < M) {
                    float v2 = acc[mf][nf][2] + bias[col];
                    float v3 = acc[mf][nf][3] + bias[col + 1];
                    if (relu) { v2 = fmaxf(v2, 0.f); v3 = fmaxf(v3, 0.f); }
                    C[(size_t)row1 * N + col] = v2;
                    C[(size_t)row1 * N + col + 1] = v3;
                }
            } else {
                float* P = part + (size_t)blockIdx.z * M * N;
                if (row0 < M) {
                    P[(size_t)row0 * N + col] = acc[mf][nf][0];
                    P[(size_t)row0 * N + col + 1] = acc[mf][nf][1];
                }
                if (row1 < M) {
                    P[(size_t)row1 * N + col] = acc[mf][nf][2];
                    P[(size_t)row1 * N + col + 1] = acc[mf][nf][3];
                }
            }
        }
    }
}

// ---------------------------------------------------------------------------
// im2col for 3x3 pad 1 conv on [512,38,63]
// ---------------------------------------------------------------------------
__global__ void im2col_kernel(const float* __restrict__ feat, float* __restrict__ col) {
    int idx = blockIdx.x * blockDim.x + threadIdx.x;
    if (idx >= NP * K_CONV) return;
    int p = idx / K_CONV;
    int k = idx - p * K_CONV;
    int ic = k / 9;
    int r = k - ic * 9;
    int ky = r / 3, kx = r - ky * 3;
    int y0 = p / WW, x0 = p - y0 * WW;
    int y = y0 + ky - 1, x = x0 + kx - 1;
    float v = 0.f;
    if (y >= 0 && y < HH && x >= 0 && x < WW)
        v = feat[ic * NP + y * WW + x];
    col[idx] = v;
}

// CHW -> HWC transpose of the input features (32x32 smem tiles)
__global__ void transpose_feat(const float* __restrict__ feat, float* __restrict__ featT) {
    __shared__ float tile[32][33];
    int p0 = blockIdx.x * 32, c0 = blockIdx.y * 32;
    int p = p0 + threadIdx.x;
    int c = c0 + threadIdx.y;
    if (p < NP) tile[threadIdx.y][threadIdx.x] = feat[(size_t)c * NP + p];
    __syncthreads();
    int pw = p0 + threadIdx.y, cw = c0 + threadIdx.x;
    if (pw < NP) featT[(size_t)pw * CIN + cw] = tile[threadIdx.x][threadIdx.y];
}

// Weight concat kernels (merge small GEMMs)
__global__ void concat_sb(const float* __restrict__ sw, const float* __restrict__ sb,
                          const float* __restrict__ bw, const float* __restrict__ bb,
                          float* __restrict__ w, float* __restrict__ b) {
    int idx = blockIdx.x * blockDim.x + threadIdx.x;
    if (idx < 54 * 512) {
        int row = idx / 512, col = idx - row * 512;
        w[idx] = (row < 18) ? sw[row * 512 + col] : bw[(row - 18) * 512 + col];
    }
    if (idx < 54) b[idx] = (idx < 18) ? sb[idx] : bb[idx - 18];
}

__global__ void concat_hd(const float* __restrict__ sfw, const float* __restrict__ sfb,
                          const float* __restrict__ bfw, const float* __restrict__ bfb,
                          float* __restrict__ w, float* __restrict__ b) {
    int idx = blockIdx.x * blockDim.x + threadIdx.x;
    if (idx < 160 * 4096) {
        int row = idx / 4096, col = idx - row * 4096;
        w[idx] = (row < 32) ? sfw[row * 4096 + col] : bfw[(row - 32) * 4096 + col];
    }
    if (idx < 160) b[idx] = (idx < 32) ? sfb[idx] : bfb[idx - 32];
}

// ---------------------------------------------------------------------------
// Scalar SGEMM (conv1, merged 1x1 conv, merged heads)
// ---------------------------------------------------------------------------
__global__ void __launch_bounds__(256, 2)
sgemm_tn(const float* __restrict__ A, const float* __restrict__ B,
         const float* __restrict__ bias, float* __restrict__ C,
         float* __restrict__ part, int M, int N, int K, int relu) {
    const int S = gridDim.z;
    const int Kc = K / S;
    const int k0 = blockIdx.z * Kc;
    const int m0 = blockIdx.x * 128;
    const int n0 = blockIdx.y * 128;

    __shared__ float As[2][8][132];
    __shared__ float Bs[2][8][132];

    const int tid = threadIdx.x;
    const int lr = tid >> 1;
    const int lc = (tid & 1) << 2;

    int arow = m0 + lr; if (arow >= M) arow = M - 1;
    int brow = n0 + lr; if (brow >= N) brow = N - 1;
    const float* Ap = A + (size_t)arow * K + k0 + lc;
    const float* Bp = B + (size_t)brow * K + k0 + lc;

    const int tx = tid & 15, ty = tid >> 4;
    const int mm = ty << 3, nn = tx << 3;

    float acc[8][8];
#pragma unroll
    for (int i = 0; i < 8; i++)
#pragma unroll
        for (int j = 0; j < 8; j++) acc[i][j] = 0.f;

    const int nIter = Kc >> 3;
    float4 a4 = *(const float4*)Ap;
    float4 b4 = *(const float4*)Bp;
    As[0][lc + 0][lr] = a4.x; As[0][lc + 1][lr] = a4.y;
    As[0][lc + 2][lr] = a4.z; As[0][lc + 3][lr] = a4.w;
    Bs[0][lc + 0][lr] = b4.x; Bs[0][lc + 1][lr] = b4.y;
    Bs[0][lc + 2][lr] = b4.z; Bs[0][lc + 3][lr] = b4.w;
    __syncthreads();

    int buf = 0;
    for (int it = 0; it < nIter; ++it) {
        float4 a4n, b4n;
        const bool more = (it + 1 < nIter);
        if (more) {
            a4n = *(const float4*)(Ap + (size_t)(it + 1) * 8);
            b4n = *(const float4*)(Bp + (size_t)(it + 1) * 8);
        }
#pragma unroll
        for (int kk = 0; kk < 8; ++kk) {
            float4 a0 = *(const float4*)&As[buf][kk][mm];
            float4 a1 = *(const float4*)&As[buf][kk][mm + 4];
            float4 b0 = *(const float4*)&Bs[buf][kk][nn];
            float4 b1 = *(const float4*)&Bs[buf][kk][nn + 4];
            float ar[8] = {a0.x, a0.y, a0.z, a0.w, a1.x, a1.y, a1.z, a1.w};
            float br[8] = {b0.x, b0.y, b0.z, b0.w, b1.x, b1.y, b1.z, b1.w};
#pragma unroll
            for (int i = 0; i < 8; i++)
#pragma unroll
                for (int j = 0; j < 8; j++) acc[i][j] += ar[i] * br[j];
        }
        if (more) {
            int nb = buf ^ 1;
            As[nb][lc + 0][lr] = a4n.x; As[nb][lc + 1][lr] = a4n.y;
            As[nb][lc + 2][lr] = a4n.z; As[nb][lc + 3][lr] = a4n.w;
            Bs[nb][lc + 0][lr] = b4n.x; Bs[nb][lc + 1][lr] = b4n.y;
            Bs[nb][lc + 2][lr] = b4n.z; Bs[nb][lc + 3][lr] = b4n.w;
            __syncthreads();
            buf = nb;
        }
    }

    if (S == 1) {
#pragma unroll
        for (int i = 0; i < 8; i++) {
            int gm = m0 + mm + i;
            if (gm >= M) continue;
#pragma unroll
            for (int j = 0; j < 8; j++) {
                int gn = n0 + nn + j;
                if (gn >= N) continue;
                float v = acc[i][j] + bias[gn];
                if (relu) v = fmaxf(v, 0.f);
                C[(size_t)gm * N + gn] = v;
            }
        }
    } else {
        float* P = part + (size_t)blockIdx.z * M * N;
#pragma unroll
        for (int i = 0; i < 8; i++) {
            int gm = m0 + mm + i;
            if (gm >= M) continue;
#pragma unroll
            for (int j = 0; j < 8; j++) {
                int gn = n0 + nn + j;
                if (gn >= N) continue;
                P[(size_t)gm * N + gn] = acc[i][j];
            }
        }
    }
}

// Deterministic split-K reduction: C = sum_z part[z] + bias (+relu)
__global__ void reduce_splits(const float* __restrict__ part, const float* __restrict__ bias,
                              float* __restrict__ C, int M, int N, int S, int relu) {
    int idx = blockIdx.x * blockDim.x + threadIdx.x;
    int total = M * N;
    if (idx >= total) return;
    float s = 0.f;
    for (int z = 0; z < S; z++) s += part[(size_t)z * total + idx];
    s += bias[idx % N];
    if (relu) s = fmaxf(s, 0.f);
    C[idx] = s;
}

// ---------------------------------------------------------------------------
// Proposal prep: reads merged sb [NP][54] (cols 0..17 score, 18..53 deltas)
// ---------------------------------------------------------------------------
__global__ void proposal_prep(const float* __restrict__ sbuf,
                              const float* __restrict__ info,
                              float* __restrict__ props, float* __restrict__ psc,
                              unsigned long long* __restrict__ keys) {
    int i = blockIdx.x * blockDim.x + threadIdx.x;
    if (i >= SORTN) return;
    if (i >= NANCH) { keys[i] = ~0ull; return; }
    int p = i / AA, a = i - p * AA;
    int hy = p / WW, wx = p - hy * WW;
    float shx = wx * 16.f, shy = hy * 16.f;
    float ax1 = c_anch[a][0] + shx, ay1 = c_anch[a][1] + shy;
    float ax2 = c_anch[a][2] + shx, ay2 = c_anch[a][3] + shy;
    float aw = ax2 - ax1 + 1.f, ah = ay2 - ay1 + 1.f;
    float cx = ax1 + 0.5f * aw, cy = ay1 + 0.5f * ah;
    const float* row = sbuf + (size_t)p * 54;
    const float* d = row + 18 + a * 4;
    float pcx = d[0] * aw + cx;
    float pcy = d[1] * ah + cy;
    float pw_ = expf(d[2]) * aw;
    float ph_ = expf(d[3]) * ah;
    float imh = info[0], imw = info[1], sc = info[2];
    float x1 = fminf(fmaxf(pcx - 0.5f * pw_, 0.f), imw - 1.f);
    float y1 = fminf(fmaxf(pcy - 0.5f * ph_, 0.f), imh - 1.f);
    float x2 = fminf(fmaxf(pcx + 0.5f * pw_, 0.f), imw - 1.f);
    float y2 = fminf(fmaxf(pcy + 0.5f * ph_, 0.f), imh - 1.f);
    bool ok = ((x2 - x1 + 1.f) >= 16.f * sc) && ((y2 - y1 + 1.f) >= 16.f * sc);
    float s0 = row[a];
    float s1 = row[a + 9];
    float m = fmaxf(s0, s1);
    float e0 = expf(s0 - m), e1 = expf(s1 - m);
    float prob = e1 / (e0 + e1);
    float score = ok ? prob : neg_inf_f();
    props[i * 4 + 0] = x1; props[i * 4 + 1] = y1;
    props[i * 4 + 2] = x2; props[i * 4 + 3] = y2;
    psc[i] = score;
    unsigned fk = fkey_asc(score);
    keys[i] = ((unsigned long long)(~fk) << 32) | (unsigned)i;
}

// ---------------------------------------------------------------------------
// Bitonic sort on 32768 u64 keys: 8192-wide local blocks + global passes.
// ---------------------------------------------------------------------------
__global__ void bitonic_local8k(unsigned long long* keys) {
    extern __shared__ unsigned long long s8[];
    int base = blockIdx.x * 8192, t = threadIdx.x;
#pragma unroll
    for (int q = 0; q < 8; q++) s8[t + q * 1024] = keys[base + t + q * 1024];
    __syncthreads();
    for (int k = 2; k <= 8192; k <<= 1) {
        for (int j = k >> 1; j > 0; j >>= 1) {
#pragma unroll
            for (int q = 0; q < 4; q++) {
                int p = t + q * 1024;
                int i = ((p & ~(j - 1)) << 1) | (p & (j - 1));
                int l = i + j;
                bool up = (((base + i) & k) == 0);
                unsigned long long a = s8[i], b = s8[l];
                if (up ? (a > b) : (a < b)) { s8[i] = b; s8[l] = a; }
            }
            __syncthreads();
        }
    }
#pragma unroll
    for (int q = 0; q < 8; q++) keys[base + t + q * 1024] = s8[t + q * 1024];
}

__global__ void bitonic_global_pass(unsigned long long* keys, int k, int j) {
    int p = blockIdx.x * blockDim.x + threadIdx.x;
    int i = ((p & ~(j - 1)) << 1) | (p & (j - 1));
    int l = i + j;
    bool up = ((i & k) == 0);
    unsigned long long a = keys[i], b = keys[l];
    if (up ? (a > b) : (a < b)) { keys[i] = b; keys[l] = a; }
}

__global__ void bitonic_tail8k(unsigned long long* keys, int k) {
    extern __shared__ unsigned long long s8[];
    int base = blockIdx.x * 8192, t = threadIdx.x;
#pragma unroll
    for (int q = 0; q < 8; q++) s8[t + q * 1024] = keys[base + t + q * 1024];
    __syncthreads();
    for (int j = 4096; j > 0; j >>= 1) {
#pragma unroll
        for (int q = 0; q < 4; q++) {
            int p = t + q * 1024;
            int i = ((p & ~(j - 1)) << 1) | (p & (j - 1));
            int l = i + j;
            bool up = (((base + i) & k) == 0);
            unsigned long long a = s8[i], b = s8[l];
            if (up ? (a > b) : (a < b)) { s8[i] = b; s8[l] = a; }
        }
        __syncthreads();
    }
#pragma unroll
    for (int q = 0; q < 8; q++) keys[base + t + q * 1024] = s8[t + q * 1024];
}

__global__ void gather_pre(const unsigned long long* __restrict__ keys,
                           const float* __restrict__ props, const float* __restrict__ psc,
                           float* __restrict__ pb, float* __restrict__ ps) {
    int i = blockIdx.x * blockDim.x + threadIdx.x;
    if (i >= PRE_NMS) return;
    unsigned idx = (unsigned)(keys[i] & 0xFFFFFFFFull);
    pb[i * 4 + 0] = props[idx * 4 + 0];
    pb[i * 4 + 1] = props[idx * 4 + 1];
    pb[i * 4 + 2] = props[idx * 4 + 2];
    pb[i * 4 + 3] = props[idx * 4 + 3];
    ps[i] = psc[idx];
}

// ---------------------------------------------------------------------------
// NMS stage 1: pairwise suppression bitmask (upper triangle: i suppresses j>i).
// Lower-triangle blocks skipped: those words are never non-zero and g_mask is
// zero-initialized (condition is data-independent), so reads stay correct.
// ---------------------------------------------------------------------------
__global__ void nms_mask_kernel(const float* __restrict__ pb,
                                unsigned long long* __restrict__ mask) {
    int jb = blockIdx.x;
    int ib = blockIdx.y;
    if (jb * 64 + 63 <= ib * 64) return;   // whole block lower-triangle
    int t = threadIdx.x;
    __shared__ float cb[64][5];
    int j0 = jb * 64;
    if (j0 + t < PRE_NMS) {
        float x1 = pb[(j0 + t) * 4 + 0];
        float y1 = pb[(j0 + t) * 4 + 1];
        float x2 = pb[(j0 + t) * 4 + 2];
        float y2 = pb[(j0 + t) * 4 + 3];
        cb[t][0] = x1; cb[t][1] = y1; cb[t][2] = x2; cb[t][3] = y2;
        cb[t][4] = (x2 - x1 + 1.f) * (y2 - y1 + 1.f);
    }
    __syncthreads();
    int i = ib * 64 + t;
    if (i >= PRE_NMS) return;
    unsigned long long w = 0ull;
    if (j0 + 63 > i) {
        float bx1 = pb[i * 4 + 0], by1 = pb[i * 4 + 1];
        float bx2 = pb[i * 4 + 2], by2 = pb[i * 4 + 3];
        float ba = (bx2 - bx1 + 1.f) * (by2 - by1 + 1.f);
        int cols = min(64, PRE_NMS - j0);
        for (int tt = 0; tt < cols; tt++) {
            int j = j0 + tt;
            if (j <= i) continue;
            float xx1 = fmaxf(bx1, cb[tt][0]);
            float yy1 = fmaxf(by1, cb[tt][1]);
            float xx2 = fminf(bx2, cb[tt][2]);
            float yy2 = fminf(by2, cb[tt][3]);
            float inter = fmaxf(xx2 - xx1 + 1.f, 0.f) * fmaxf(yy2 - yy1 + 1.f, 0.f);
            float iou = inter / (ba + cb[tt][4] - inter);
            if (iou > 0.7f) w |= (1ull << tt);
        }
    }
    mask[(size_t)i * NWRD + jb] = w;
}

// ---------------------------------------------------------------------------
// NMS stage 2: block-parallel greedy scan over an alive bitmap.
// ---------------------------------------------------------------------------
__global__ void nms_scan2(const unsigned long long* __restrict__ mask,
                          const float* __restrict__ pb,
                          const float* __restrict__ ps,
                          float* __restrict__ rois, float* __restrict__ out_rois) {
    __shared__ unsigned alive[NW32];
    __shared__ int wmin[8];
    __shared__ int s_best, s_kept;
    int t = threadIdx.x;
    int lane = t & 31, wid = t >> 5;

    for (int w = wid; w < NW32; w += 8) {
        int c = w * 32 + lane;
        bool fin = (c < PRE_NMS) && (ps[c] > -3.0e38f);
        unsigned m = __ballot_sync(0xFFFFFFFFu, fin);
        if (lane == 0) alive[w] = m;
    }
    if (t == 0) s_kept = 0;
    __syncthreads();

    for (int r = 0; r < POST_NMS; r++) {
        int cand = 0x7FFFFFFF;
        if (t < NW32) {
            unsigned w = alive[t];
            if (w) cand = t * 32 + __ffs(w) - 1;
        }
#pragma unroll
        for (int o = 16; o; o >>= 1) cand = min(cand, __shfl_xor_sync(0xFFFFFFFFu, cand, o));
        if (lane == 0) wmin[wid] = cand;
        __syncthreads();
        if (t == 0) {
            int b = wmin[0];
#pragma unroll
            for (int q = 1; q < 8; q++) b = min(b, wmin[q]);
            s_best = b;
        }
        __syncthreads();
        int i = s_best;
        if (i == 0x7FFFFFFF) break;
        if (t == 0) {
            float x1 = pb[i * 4 + 0], y1 = pb[i * 4 + 1];
            float x2 = pb[i * 4 + 2], y2 = pb[i * 4 + 3];
            rois[r * 4 + 0] = x1; rois[r * 4 + 1] = y1;
            rois[r * 4 + 2] = x2; rois[r * 4 + 3] = y2;
            out_rois[r * 4 + 0] = x1; out_rois[r * 4 + 1] = y1;
            out_rois[r * 4 + 2] = x2; out_rois[r * 4 + 3] = y2;
            s_kept = r + 1;
        }
        if (t < NW32) {
            const unsigned* row = (const unsigned*)(mask + (size_t)i * NWRD);
            unsigned a = alive[t] & ~row[t];
            if (t == (i >> 5)) a &= ~(1u << (i & 31));
            alive[t] = a;
        }
        __syncthreads();
    }
    __syncthreads();
    if (t == 0) {
        int kept = s_kept;
        float x1 = pb[0], y1 = pb[1], x2 = pb[2], y2 = pb[3];
        for (int r = kept; r < POST_NMS; r++) {
            rois[r * 4 + 0] = x1; rois[r * 4 + 1] = y1;
            rois[r * 4 + 2] = x2; rois[r * 4 + 3] = y2;
            out_rois[r * 4 + 0] = x1; out_rois[r * 4 + 1] = y1;
            out_rois[r * 4 + 2] = x2; out_rois[r * 4 + 3] = y2;
        }
    }
}

// ---------------------------------------------------------------------------
// ROI max-pool 7x7, HWC layout: block per (roi, bin-row). 128 threads x 4
// channels (float4). Bin boundaries and per-channel max order identical to
// reference — pure work partitioning across blocks.
// ---------------------------------------------------------------------------
__global__ void __launch_bounds__(128)
roipool_hwc(const float* __restrict__ featT, const float* __restrict__ rois,
            float* __restrict__ pooled) {
    int r = blockIdx.x;
    int ph = blockIdx.y;
    int t = threadIdx.x;
    __shared__ int hs, he, ws_[7], we[7];
    if (t == 0) {
        float x1 = rois[r * 4], y1 = rois[r * 4 + 1], x2 = rois[r * 4 + 2], y2 = rois[r * 4 + 3];
        float rsw = rintf(x1 * 0.0625f), rsh = rintf(y1 * 0.0625f);
        float rew = rintf(x2 * 0.0625f), reh = rintf(y2 * 0.0625f);
        float bw = fmaxf(rew - rsw + 1.f, 1.f) * (1.f / 7.f);
        float bh = fmaxf(reh - rsh + 1.f, 1.f) * (1.f / 7.f);
        float fp = (float)ph;
        hs = (int)fminf(fmaxf(floorf(fp * bh) + rsh, 0.f), (float)HH);
        he = (int)fminf(fmaxf(ceilf((fp + 1.f) * bh) + rsh, 0.f), (float)HH);
        for (int p = 0; p < 7; p++) {
            float fq = (float)p;
            ws_[p] = (int)fminf(fmaxf(floorf(fq * bw) + rsw, 0.f), (float)WW);
            we[p] = (int)fminf(fmaxf(ceilf((fq + 1.f) * bw) + rsw, 0.f), (float)WW);
        }
    }
    __syncthreads();
    const float4* fT = (const float4*)featT;    // [pix][128] float4
    float* dst = pooled + (size_t)r * K_FC6;
    int c = 4 * t;
#pragma unroll 1
    for (int pw = 0; pw < 7; pw++) {
        int bin = ph * 7 + pw;
        float4 m = make_float4(-1e30f, -1e30f, -1e30f, -1e30f);
        for (int y = hs; y < he; y++) {
            const float4* rowp = fT + (size_t)(y * WW) * 128 + t;
            for (int x = ws_[pw]; x < we[pw]; x++) {
                float4 v = rowp[(size_t)x * 128];
                m.x = fmaxf(m.x, v.x);
                m.y = fmaxf(m.y, v.y);
                m.z = fmaxf(m.z, v.z);
                m.w = fmaxf(m.w, v.w);
            }
        }
        dst[(c + 0) * 49 + bin] = (m.x < -1e29f) ? 0.f : m.x;
        dst[(c + 1) * 49 + bin] = (m.y < -1e29f) ? 0.f : m.y;
        dst[(c + 2) * 49 + bin] = (m.z < -1e29f) ? 0.f : m.z;
        dst[(c + 3) * 49 + bin] = (m.w < -1e29f) ? 0.f : m.w;
    }
}

// ---------------------------------------------------------------------------
// Heads output: softmax over 32 classes (warp 0) + box copy (threads 32..159)
// ---------------------------------------------------------------------------
__global__ void heads_out(const float* __restrict__ hd, float* __restrict__ out) {
    int r = blockIdx.x;
    int t = threadIdx.x;
    if (t < 32) {
        float v = hd[r * 160 + t];
        float m = v;
#pragma unroll
        for (int o = 16; o; o >>= 1) m = fmaxf(m, __shfl_xor_sync(0xFFFFFFFFu, m, o));
        float e = expf(v - m);
        float s = e;
#pragma unroll
        for (int o = 16; o; o >>= 1) s += __shfl_xor_sync(0xFFFFFFFFu, s, o);
        out[r * NCLS + t] = e / s;
    } else {
        out[9600 + r * 128 + (t - 32)] = hd[r * 160 + t];
    }
}

// ---------------------------------------------------------------------------
// Launch
// ---------------------------------------------------------------------------
extern "C" void kernel_launch(void* const* d_in, const int* in_sizes, int n_in,
                              void* d_out, int out_size) {
    const float* feat  = (const float*)d_in[0];
    const float* info  = (const float*)d_in[1];
    const float* c1w   = (const float*)d_in[2];
    const float* c1b   = (const float*)d_in[3];
    const float* sw    = (const float*)d_in[4];
    const float* sb    = (const float*)d_in[5];
    const float* bw    = (const float*)d_in[6];
    const float* bb    = (const float*)d_in[7];
    const float* fc6w  = (const float*)d_in[8];
    const float* fc6b  = (const float*)d_in[9];
    const float* fc7w  = (const float*)d_in[10];
    const float* fc7b  = (const float*)d_in[11];
    const float* sfw   = (const float*)d_in[12];
    const float* sfb   = (const float*)d_in[13];
    const float* bfw   = (const float*)d_in[14];
    const float* bfb   = (const float*)d_in[15];
    float* out = (float*)d_out;

    float *col, *rpn, *featT, *sbuf, *sbw, *sbb, *hw, *hb, *hd, *part, *part2;
    float *props, *psc, *pbv, *psv, *rois, *pooled, *x6, *x7;
    unsigned long long *keys, *mask;
    cudaGetSymbolAddress((void**)&col, g_col);
    cudaGetSymbolAddress((void**)&rpn, g_rpn);
    cudaGetSymbolAddress((void**)&featT, g_featT);
    cudaGetSymbolAddress((void**)&sbuf, g_sb);
    cudaGetSymbolAddress((void**)&sbw, g_sbw);
    cudaGetSymbolAddress((void**)&sbb, g_sbb);
    cudaGetSymbolAddress((void**)&hw, g_hw);
    cudaGetSymbolAddress((void**)&hb, g_hb);
    cudaGetSymbolAddress((void**)&hd, g_hd);
    cudaGetSymbolAddress((void**)&part, g_part);
    cudaGetSymbolAddress((void**)&part2, g_part2);
    cudaGetSymbolAddress((void**)&props, g_props);
    cudaGetSymbolAddress((void**)&psc, g_psc);
    cudaGetSymbolAddress((void**)&keys, g_keys);
    cudaGetSymbolAddress((void**)&pbv, g_pb);
    cudaGetSymbolAddress((void**)&psv, g_ps);
    cudaGetSymbolAddress((void**)&mask, g_mask);
    cudaGetSymbolAddress((void**)&rois, g_rois);
    cudaGetSymbolAddress((void**)&pooled, g_pooled);
    cudaGetSymbolAddress((void**)&x6, g_x6);
    cudaGetSymbolAddress((void**)&x7, g_x7);

    const int MT_NP = (NP + 127) / 128;   // 19

    cudaFuncSetAttribute(mma_gemm, cudaFuncAttributeMaxDynamicSharedMemorySize, MM2_SMEM);
    cudaFuncSetAttribute(bitonic_local8k, cudaFuncAttributeMaxDynamicSharedMemorySize, 65536);
    cudaFuncSetAttribute(bitonic_tail8k, cudaFuncAttributeMaxDynamicSharedMemorySize, 65536);

    // 0. weight concats + feature transpose (input-only deps)
    concat_sb<<<(54 * 512 + 255) / 256, 256>>>(sw, sb, bw, bb, sbw, sbb);
    concat_hd<<<(160 * 4096 + 255) / 256, 256>>>(sfw, sfb, bfw, bfb, hw, hb);
    {
        dim3 gt((NP + 31) / 32, CIN / 32);
        transpose_feat<<<gt, dim3(32, 32)>>>(feat, featT);
    }

    // 1. im2col + conv1 (split-K S=4 scalar GEMM) + relu -> rpn (HWC)
    {
        int total = NP * K_CONV;
        im2col_kernel<<<(total + 255) / 256, 256>>>(feat, col);
        dim3 grid(MT_NP, 4, 4);  // Kc = 1152, 304 CTAs
        sgemm_tn<<<grid, 256>>>(col, c1w, c1b, rpn, part2, NP, CIN, K_CONV, 1);
        reduce_splits<<<(NP * CIN + 255) / 256, 256>>>(part2, c1b, rpn, NP, CIN, 4, 1);
    }
    // 2. merged score+bbox 1x1 conv (N=54)
    {
        dim3 g1(MT_NP, 1, 4);  // Kc = 128
        sgemm_tn<<<g1, 256>>>(rpn, sbw, sbb, sbuf, part2, NP, 54, CIN, 0);
        reduce_splits<<<(NP * 54 + 255) / 256, 256>>>(part2, sbb, sbuf, NP, 54, 4, 0);
    }
    // 3. proposals + sort keys
    proposal_prep<<<SORTN / 256, 256>>>(sbuf, info, props, psc, keys);
    // 4. bitonic sort (6 launches)
    bitonic_local8k<<<4, 1024, 65536>>>(keys);
    bitonic_global_pass<<<SORTN / 2 / 256, 256>>>(keys, 16384, 8192);
    bitonic_tail8k<<<4, 1024, 65536>>>(keys, 16384);
    bitonic_global_pass<<<SORTN / 2 / 256, 256>>>(keys, 32768, 16384);
    bitonic_global_pass<<<SORTN / 2 / 256, 256>>>(keys, 32768, 8192);
    bitonic_tail8k<<<4, 1024, 65536>>>(keys, 32768);
    // 5. gather top-6000
    gather_pre<<<(PRE_NMS + 255) / 256, 256>>>(keys, props, psc, pbv, psv);
    // 6. NMS: pairwise mask (upper triangle only) + block-parallel bitmap scan
    {
        dim3 gm(NWRD, NWRD);
        nms_mask_kernel<<<gm, 64>>>(pbv, mask);
        nms_scan2<<<1, 256>>>(mask, pbv, psv, rois, out + 48000);
    }
    // 7. ROI pool (HWC float4, block per (roi, bin-row) for 7x parallelism)
    {
        dim3 gr(POST_NMS, 7);
        roipool_hwc<<<gr, 128>>>(featT, rois, pooled);
    }
    // 8. FC stack: fc6/fc7 HMMA bf16-split (ldmatrix); wave-balanced split-K
    {
        dim3 g6(5, 32, 7);   // Kc = 3584 (112 chunks), 1120 CTAs (3.78 waves @296)
        mma_gemm<<<g6, 256, MM2_SMEM>>>(pooled, fc6w, fc6b, x6, part, POST_NMS, 4096, K_FC6, 1);
        reduce_splits<<<(POST_NMS * 4096 + 255) / 256, 256>>>(part, fc6b, x6, POST_NMS, 4096, 7, 1);

        dim3 g7(5, 32, 8);   // Kc = 512 (16 chunks), 1280 CTAs (4.32 waves)
        mma_gemm<<<g7, 256, MM2_SMEM>>>(x6, fc7w, fc7b, x7, part, POST_NMS, 4096, 4096, 1);
        reduce_splits<<<(POST_NMS * 4096 + 255) / 256, 256>>>(part, fc7b, x7, POST_NMS, 4096, 8, 1);

        dim3 gh(3, 2, 4);    // merged heads N=160, Kc = 1024
        sgemm_tn<<<gh, 256>>>(x7, hw, hb, hd, part, POST_NMS, 160, 4096, 0);
        reduce_splits<<<(POST_NMS * 160 + 255) / 256, 256>>>(part, hb, hd, POST_NMS, 160, 4, 0);
    }
    // 9. cls softmax + box copy -> out
    heads_out<<<POST_NMS, 160>>>(hd, out);
}